// round 1
// baseline (speedup 1.0000x reference)
#include <cuda_runtime.h>

#define NN 40000
#define NE 640000
#define D  128
#define TILE 64
#define NTHREADS 256

// Scratch (allocation-free rule: __device__ globals)
__device__ float g_e1[(size_t)NE * D];   // 327.7 MB
__device__ float g_x1[(size_t)NN * D];   // 20.5 MB

struct Smem {
    float sA[TILE * 384];   // 96 KB  (concat input, stride up to 384)
    float sW[64 * 128];     // 32 KB  (weight K-chunk)
    float sH[TILE * 128];   // 32 KB  (hidden activations)
    int   sRow[TILE];
    int   sCol[TILE];
};

__device__ __forceinline__ void gemm_chunk(const float* __restrict__ sIn, int stride, int kBase,
                                           const float* __restrict__ sW,
                                           float (&C)[4][8], int m0, int n0)
{
#pragma unroll 2
    for (int k = 0; k < 64; k += 4) {
        float a[4][4];
#pragma unroll
        for (int i = 0; i < 4; i++) {
            float4 v = *(const float4*)&sIn[(m0 + i) * stride + kBase + k];
            a[i][0] = v.x; a[i][1] = v.y; a[i][2] = v.z; a[i][3] = v.w;
        }
#pragma unroll
        for (int t = 0; t < 4; t++) {
            float4 w0 = *(const float4*)&sW[(k + t) * 128 + n0];
            float4 w1 = *(const float4*)&sW[(k + t) * 128 + n0 + 4];
            float w[8] = {w0.x, w0.y, w0.z, w0.w, w1.x, w1.y, w1.z, w1.w};
#pragma unroll
            for (int i = 0; i < 4; i++)
#pragma unroll
                for (int j = 0; j < 8; j++)
                    C[i][j] = fmaf(a[i][t], w[j], C[i][j]);
        }
    }
}

__device__ __forceinline__ void load_w(const float* __restrict__ W, int k0, float* sW)
{
    const float4* src = (const float4*)(W + (size_t)k0 * 128);
    float4* dst = (float4*)sW;
    for (int i = threadIdx.x; i < 64 * 32; i += NTHREADS)
        dst[i] = src[i];
}

// 2-layer MLP: out = relu(In @ w1 + b1) @ w2 + b2, In is [64, K1] in smem.
template<int K1>
__device__ __forceinline__ void run_mlp(Smem* sm, const float* sIn, int stride,
        const float* __restrict__ w1, const float* __restrict__ b1,
        const float* __restrict__ w2, const float* __restrict__ b2,
        float (&C)[4][8], int m0, int n0)
{
#pragma unroll
    for (int i = 0; i < 4; i++)
#pragma unroll
        for (int j = 0; j < 8; j++) C[i][j] = 0.f;

    for (int k0 = 0; k0 < K1; k0 += 64) {
        __syncthreads();              // protect sW from previous readers; publish sIn writes
        load_w(w1, k0, sm->sW);
        __syncthreads();
        gemm_chunk(sIn, stride, k0, sm->sW, C, m0, n0);
    }

    // bias + relu -> sH
#pragma unroll
    for (int i = 0; i < 4; i++)
#pragma unroll
        for (int j = 0; j < 8; j++) {
            float v = C[i][j] + b1[n0 + j];
            sm->sH[(m0 + i) * 128 + n0 + j] = fmaxf(v, 0.f);
        }

#pragma unroll
    for (int i = 0; i < 4; i++)
#pragma unroll
        for (int j = 0; j < 8; j++) C[i][j] = 0.f;

    for (int k0 = 0; k0 < 128; k0 += 64) {
        __syncthreads();              // also publishes sH writes before first read
        load_w(w2, k0, sm->sW);
        __syncthreads();
        gemm_chunk(sm->sH, 128, k0, sm->sW, C, m0, n0);
    }
#pragma unroll
    for (int i = 0; i < 4; i++)
#pragma unroll
        for (int j = 0; j < 8; j++) C[i][j] += b2[n0 + j];
}

__global__ void zero_kernel(float* __restrict__ x2out)
{
    size_t n = (size_t)NN * D;
    for (size_t i = (size_t)blockIdx.x * blockDim.x + threadIdx.x; i < n;
         i += (size_t)gridDim.x * blockDim.x) {
        g_x1[i] = 0.f;
        x2out[i] = 0.f;
    }
}

// Phase A: e1 = MLP1([x[row], x[col], ea]); msg = MLP2([x[row], e1]); x1 += scatter(msg, col)
__global__ void __launch_bounds__(NTHREADS, 1)
phaseA_kernel(const float* __restrict__ x, const float* __restrict__ ea,
              const int* __restrict__ row, const int* __restrict__ col,
              const float* __restrict__ e1w1, const float* __restrict__ e1b1,
              const float* __restrict__ e1w2, const float* __restrict__ e1b2,
              const float* __restrict__ n1w1, const float* __restrict__ n1b1,
              const float* __restrict__ n1w2, const float* __restrict__ n1b2)
{
    extern __shared__ char smem_raw[];
    Smem* sm = (Smem*)smem_raw;
    const int tid = threadIdx.x;
    const int e0 = blockIdx.x * TILE;

    if (tid < TILE) sm->sRow[tid] = row[e0 + tid];
    else if (tid < 2 * TILE) sm->sCol[tid - TILE] = col[e0 + tid - TILE];
    __syncthreads();

    for (int i = tid; i < TILE * 32; i += NTHREADS) {
        int e = i >> 5, c = (i & 31) * 4;
        *(float4*)&sm->sA[e * 384 + c] = *(const float4*)&x[(size_t)sm->sRow[e] * D + c];
    }
    for (int i = tid; i < TILE * 32; i += NTHREADS) {
        int e = i >> 5, c = (i & 31) * 4;
        *(float4*)&sm->sA[e * 384 + 128 + c] = *(const float4*)&x[(size_t)sm->sCol[e] * D + c];
    }
    for (int i = tid; i < TILE * 32; i += NTHREADS) {
        int e = i >> 5, c = (i & 31) * 4;
        *(float4*)&sm->sA[e * 384 + 256 + c] = *(const float4*)&ea[(size_t)(e0 + e) * D + c];
    }

    const int n0 = (tid & 15) * 8;
    const int m0 = (tid >> 4) * 4;
    float C[4][8];

    run_mlp<384>(sm, sm->sA, 384, e1w1, e1b1, e1w2, e1b2, C, m0, n0);

    // e1 -> global scratch AND into sA cols [128,256) (overwrites x[col], keeps x[row])
#pragma unroll
    for (int i = 0; i < 4; i++) {
        int e = m0 + i;
#pragma unroll
        for (int j = 0; j < 8; j += 4) {
            float4 v = make_float4(C[i][j], C[i][j+1], C[i][j+2], C[i][j+3]);
            *(float4*)&sm->sA[e * 384 + 128 + n0 + j] = v;
            *(float4*)&g_e1[(size_t)(e0 + e) * D + n0 + j] = v;
        }
    }

    run_mlp<256>(sm, sm->sA, 384, n1w1, n1b1, n1w2, n1b2, C, m0, n0);

#pragma unroll
    for (int i = 0; i < 4; i++) {
        float* dst = &g_x1[(size_t)sm->sCol[m0 + i] * D + n0];
#pragma unroll
        for (int j = 0; j < 8; j++)
            atomicAdd(dst + j, C[i][j]);
    }
}

// Phase B: msg2 = MLP3([x1[row], e1]); x2 += scatter(msg2, col)
__global__ void __launch_bounds__(NTHREADS, 1)
phaseB_kernel(const int* __restrict__ row, const int* __restrict__ col,
              const float* __restrict__ n2w1, const float* __restrict__ n2b1,
              const float* __restrict__ n2w2, const float* __restrict__ n2b2,
              float* __restrict__ x2out)
{
    extern __shared__ char smem_raw[];
    Smem* sm = (Smem*)smem_raw;
    const int tid = threadIdx.x;
    const int e0 = blockIdx.x * TILE;

    if (tid < TILE) sm->sRow[tid] = row[e0 + tid];
    else if (tid < 2 * TILE) sm->sCol[tid - TILE] = col[e0 + tid - TILE];
    __syncthreads();

    for (int i = tid; i < TILE * 32; i += NTHREADS) {
        int e = i >> 5, c = (i & 31) * 4;
        *(float4*)&sm->sA[e * 256 + c] = *(const float4*)&g_x1[(size_t)sm->sRow[e] * D + c];
    }
    for (int i = tid; i < TILE * 32; i += NTHREADS) {
        int e = i >> 5, c = (i & 31) * 4;
        *(float4*)&sm->sA[e * 256 + 128 + c] = *(const float4*)&g_e1[(size_t)(e0 + e) * D + c];
    }

    const int n0 = (tid & 15) * 8;
    const int m0 = (tid >> 4) * 4;
    float C[4][8];

    run_mlp<256>(sm, sm->sA, 256, n2w1, n2b1, n2w2, n2b2, C, m0, n0);

#pragma unroll
    for (int i = 0; i < 4; i++) {
        float* dst = &x2out[(size_t)sm->sCol[m0 + i] * D + n0];
#pragma unroll
        for (int j = 0; j < 8; j++)
            atomicAdd(dst + j, C[i][j]);
    }
}

// Phase C: e2 = MLP4([x2[row], x2[col], e1])
__global__ void __launch_bounds__(NTHREADS, 1)
phaseC_kernel(const int* __restrict__ row, const int* __restrict__ col,
              const float* __restrict__ e2w1, const float* __restrict__ e2b1,
              const float* __restrict__ e2w2, const float* __restrict__ e2b2,
              const float* __restrict__ x2in, float* __restrict__ e2out)
{
    extern __shared__ char smem_raw[];
    Smem* sm = (Smem*)smem_raw;
    const int tid = threadIdx.x;
    const int e0 = blockIdx.x * TILE;

    if (tid < TILE) sm->sRow[tid] = row[e0 + tid];
    else if (tid < 2 * TILE) sm->sCol[tid - TILE] = col[e0 + tid - TILE];
    __syncthreads();

    for (int i = tid; i < TILE * 32; i += NTHREADS) {
        int e = i >> 5, c = (i & 31) * 4;
        *(float4*)&sm->sA[e * 384 + c] = *(const float4*)&x2in[(size_t)sm->sRow[e] * D + c];
    }
    for (int i = tid; i < TILE * 32; i += NTHREADS) {
        int e = i >> 5, c = (i & 31) * 4;
        *(float4*)&sm->sA[e * 384 + 128 + c] = *(const float4*)&x2in[(size_t)sm->sCol[e] * D + c];
    }
    for (int i = tid; i < TILE * 32; i += NTHREADS) {
        int e = i >> 5, c = (i & 31) * 4;
        *(float4*)&sm->sA[e * 384 + 256 + c] = *(const float4*)&g_e1[(size_t)(e0 + e) * D + c];
    }

    const int n0 = (tid & 15) * 8;
    const int m0 = (tid >> 4) * 4;
    float C[4][8];

    run_mlp<384>(sm, sm->sA, 384, e2w1, e2b1, e2w2, e2b2, C, m0, n0);

#pragma unroll
    for (int i = 0; i < 4; i++) {
        int e = m0 + i;
#pragma unroll
        for (int j = 0; j < 8; j += 4) {
            float4 v = make_float4(C[i][j], C[i][j+1], C[i][j+2], C[i][j+3]);
            *(float4*)&e2out[(size_t)(e0 + e) * D + n0 + j] = v;
        }
    }
}

extern "C" void kernel_launch(void* const* d_in, const int* in_sizes, int n_in,
                              void* d_out, int out_size)
{
    const float* x    = (const float*)d_in[0];
    const float* ea   = (const float*)d_in[1];
    const int*   ei   = (const int*)d_in[2];
    const float* e1w1 = (const float*)d_in[3];
    const float* e1b1 = (const float*)d_in[4];
    const float* e1w2 = (const float*)d_in[5];
    const float* e1b2 = (const float*)d_in[6];
    const float* n1w1 = (const float*)d_in[7];
    const float* n1b1 = (const float*)d_in[8];
    const float* n1w2 = (const float*)d_in[9];
    const float* n1b2 = (const float*)d_in[10];
    const float* n2w1 = (const float*)d_in[11];
    const float* n2b1 = (const float*)d_in[12];
    const float* n2w2 = (const float*)d_in[13];
    const float* n2b2 = (const float*)d_in[14];
    const float* e2w1 = (const float*)d_in[15];
    const float* e2b1 = (const float*)d_in[16];
    const float* e2w2 = (const float*)d_in[17];
    const float* e2b2 = (const float*)d_in[18];

    const int* row = ei;            // edge_index[0] = source
    const int* col = ei + NE;       // edge_index[1] = target

    float* out = (float*)d_out;
    float* x2  = out;                         // [NN, D]
    float* e2o = out + (size_t)NN * D;        // [NE, D]

    int smemBytes = (int)sizeof(Smem);
    cudaFuncSetAttribute(phaseA_kernel, cudaFuncAttributeMaxDynamicSharedMemorySize, smemBytes);
    cudaFuncSetAttribute(phaseB_kernel, cudaFuncAttributeMaxDynamicSharedMemorySize, smemBytes);
    cudaFuncSetAttribute(phaseC_kernel, cudaFuncAttributeMaxDynamicSharedMemorySize, smemBytes);

    zero_kernel<<<512, NTHREADS>>>(x2);
    phaseA_kernel<<<NE / TILE, NTHREADS, smemBytes>>>(x, ea, row, col,
        e1w1, e1b1, e1w2, e1b2, n1w1, n1b1, n1w2, n1b2);
    phaseB_kernel<<<NE / TILE, NTHREADS, smemBytes>>>(row, col,
        n2w1, n2b1, n2w2, n2b2, x2);
    phaseC_kernel<<<NE / TILE, NTHREADS, smemBytes>>>(row, col,
        e2w1, e2b1, e2w2, e2b2, x2, e2o);
}

// round 2
// speedup vs baseline: 2.1661x; 2.1661x over previous
#include <cuda_runtime.h>
#include <cuda_bf16.h>
#include <cstdint>

#define NN 40000
#define NE 640000
#define TILE 64
#define NTH 256
#define SA 392   // A-plane smem stride (halves): 784B -> %128==16, ldmatrix conflict-free
#define SW 72    // W-plane smem stride (halves): 144B -> %128==16, conflict-free

typedef __nv_bfloat16 bf16;
typedef unsigned int u32;

// ---- device scratch (no allocations allowed) ----
__device__ bf16  g_e1h[(size_t)NE * 128];
__device__ bf16  g_e1l[(size_t)NE * 128];
__device__ float g_x1[(size_t)NN * 128];
__device__ bf16  g_wh[229376];   // all 8 weight mats, transposed [n][k], hi plane
__device__ bf16  g_wl[229376];   // lo plane

// offsets (elements) into g_wh/g_wl: order e1w1,e1w2,n1w1,n1w2,n2w1,n2w2,e2w1,e2w2
#define W_E1W1 0
#define W_E1W2 49152
#define W_N1W1 65536
#define W_N1W2 98304
#define W_N2W1 114688
#define W_N2W2 147456
#define W_E2W1 163840
#define W_E2W2 212992

struct SM {
    bf16 Ah[TILE * SA];   // 50176 B
    bf16 Al[TILE * SA];   // 50176 B
    bf16 Wh[128 * SW];    // 18432 B
    bf16 Wl[128 * SW];    // 18432 B
    float b1[128];
    float b2[128];
    int rowI[TILE];
    int colI[TILE];
};                        // ~138.8 KB

// ---- helpers ----
__device__ __forceinline__ u32 cvta(const void* p) {
    return (u32)__cvta_generic_to_shared(p);
}

__device__ __forceinline__ void ldsm4(u32 addr, u32& r0, u32& r1, u32& r2, u32& r3) {
    asm volatile("ldmatrix.sync.aligned.m8n8.x4.shared.b16 {%0,%1,%2,%3}, [%4];"
                 : "=r"(r0), "=r"(r1), "=r"(r2), "=r"(r3) : "r"(addr));
}

__device__ __forceinline__ void mma16816(float* c, const u32* a, const u32* b) {
    asm volatile("mma.sync.aligned.m16n8k16.row.col.f32.bf16.bf16.f32 "
                 "{%0,%1,%2,%3}, {%4,%5,%6,%7}, {%8,%9}, {%0,%1,%2,%3};"
                 : "+f"(c[0]), "+f"(c[1]), "+f"(c[2]), "+f"(c[3])
                 : "r"(a[0]), "r"(a[1]), "r"(a[2]), "r"(a[3]), "r"(b[0]), "r"(b[1]));
}

__device__ __forceinline__ void split2(float x, bf16& h, bf16& l) {
    h = __float2bfloat16_rn(x);
    l = __float2bfloat16_rn(x - __bfloat162float(h));
}

__device__ __forceinline__ void store_split4(bf16* ph, bf16* pl, float4 v) {
    bf16 h0,l0,h1,l1,h2,l2,h3,l3;
    split2(v.x,h0,l0); split2(v.y,h1,l1); split2(v.z,h2,l2); split2(v.w,h3,l3);
    __nv_bfloat162 t;
    t.x=h0; t.y=h1; ((__nv_bfloat162*)ph)[0]=t;
    t.x=h2; t.y=h3; ((__nv_bfloat162*)ph)[1]=t;
    t.x=l0; t.y=l1; ((__nv_bfloat162*)pl)[0]=t;
    t.x=l2; t.y=l3; ((__nv_bfloat162*)pl)[1]=t;
}

__device__ __forceinline__ void store_h2(bf16* ph, bf16* pl, float x0, float x1) {
    bf16 h0,l0,h1,l1; split2(x0,h0,l0); split2(x1,h1,l1);
    __nv_bfloat162 t;
    t.x=h0; t.y=h1; *(__nv_bfloat162*)ph = t;
    t.x=l0; t.y=l1; *(__nv_bfloat162*)pl = t;
}

// GEMM: C[64 x 128] += A(smem planes, cols [aCol, aCol+K)) x W^T(global split) ; bias staged too
__device__ __forceinline__ void run_gemm(SM* sm, int aCol, int K,
    const bf16* __restrict__ gwh, const bf16* __restrict__ gwl,
    const float* __restrict__ bias, float* sBias, float C[2][4][4])
{
    const int tid = threadIdx.x, lane = tid & 31, wid = tid >> 5;
    const int wM = wid >> 2, wN = wid & 3;
#pragma unroll
    for (int i = 0; i < 2; i++)
#pragma unroll
        for (int j = 0; j < 4; j++)
#pragma unroll
            for (int q = 0; q < 4; q++) C[i][j][q] = 0.f;

    const u32 ah_base = cvta(sm->Ah), al_base = cvta(sm->Al);
    const u32 wh_base = cvta(sm->Wh), wl_base = cvta(sm->Wl);

    const int aRow0 = wM * 32 + (lane & 15);
    const int aColL = (lane >> 4) * 8;
    const int bRowL = (lane & 7) + ((lane & 16) >> 1);
    const int bColL = (lane & 8);

    for (int k0 = 0; k0 < K; k0 += 64) {
        __syncthreads();
        for (int i = tid; i < 1024; i += NTH) {
            int r = i >> 3, s = (i & 7) << 3;
            *(uint4*)&sm->Wh[r * SW + s] = *(const uint4*)&gwh[(size_t)r * K + k0 + s];
            *(uint4*)&sm->Wl[r * SW + s] = *(const uint4*)&gwl[(size_t)r * K + k0 + s];
        }
        if (k0 == 0 && tid < 128) sBias[tid] = bias[tid];
        __syncthreads();
#pragma unroll
        for (int kk = 0; kk < 64; kk += 16) {
            u32 a_h[2][4], a_l[2][4];
#pragma unroll
            for (int mi = 0; mi < 2; mi++) {
                u32 off = (u32)(((aRow0 + mi * 16) * SA + aCol + k0 + kk + aColL) * 2);
                ldsm4(ah_base + off, a_h[mi][0], a_h[mi][1], a_h[mi][2], a_h[mi][3]);
                ldsm4(al_base + off, a_l[mi][0], a_l[mi][1], a_l[mi][2], a_l[mi][3]);
            }
            u32 b_h[4][2], b_l[4][2];
#pragma unroll
            for (int pr = 0; pr < 2; pr++) {
                u32 off = (u32)(((wN * 32 + pr * 16 + bRowL) * SW + kk + bColL) * 2);
                ldsm4(wh_base + off, b_h[2*pr][0], b_h[2*pr][1], b_h[2*pr+1][0], b_h[2*pr+1][1]);
                ldsm4(wl_base + off, b_l[2*pr][0], b_l[2*pr][1], b_l[2*pr+1][0], b_l[2*pr+1][1]);
            }
#pragma unroll
            for (int mi = 0; mi < 2; mi++)
#pragma unroll
                for (int nb = 0; nb < 4; nb++) {
                    mma16816(C[mi][nb], a_h[mi], b_h[nb]);
                    mma16816(C[mi][nb], a_l[mi], b_h[nb]);
                    mma16816(C[mi][nb], a_h[mi], b_l[nb]);
                }
        }
    }
}

// hidden = relu(C + b1) -> split -> smem cols [256,384)
__device__ __forceinline__ void hidden_epilogue(SM* sm, float C[2][4][4]) {
    const int lane = threadIdx.x & 31, wid = threadIdx.x >> 5;
    const int wM = wid >> 2, wN = wid & 3, g = lane >> 2, q = (lane & 3) * 2;
#pragma unroll
    for (int mi = 0; mi < 2; mi++)
#pragma unroll
        for (int nb = 0; nb < 4; nb++) {
            int r = wM * 32 + mi * 16 + g, c = wN * 32 + nb * 8 + q;
            float b0 = sm->b1[c], b1v = sm->b1[c + 1];
            store_h2(&sm->Ah[r * SA + 256 + c], &sm->Al[r * SA + 256 + c],
                     fmaxf(C[mi][nb][0] + b0, 0.f), fmaxf(C[mi][nb][1] + b1v, 0.f));
            store_h2(&sm->Ah[(r + 8) * SA + 256 + c], &sm->Al[(r + 8) * SA + 256 + c],
                     fmaxf(C[mi][nb][2] + b0, 0.f), fmaxf(C[mi][nb][3] + b1v, 0.f));
        }
}

__device__ __forceinline__ void scatter_epilogue(SM* sm, float C[2][4][4], float* __restrict__ dst) {
    const int lane = threadIdx.x & 31, wid = threadIdx.x >> 5;
    const int wM = wid >> 2, wN = wid & 3, g = lane >> 2, q = (lane & 3) * 2;
#pragma unroll
    for (int mi = 0; mi < 2; mi++)
#pragma unroll
        for (int nb = 0; nb < 4; nb++) {
            int r = wM * 32 + mi * 16 + g, c = wN * 32 + nb * 8 + q;
            float b0 = sm->b2[c], b1v = sm->b2[c + 1];
            float* d0 = dst + (size_t)sm->colI[r] * 128 + c;
            atomicAdd(d0,     C[mi][nb][0] + b0);
            atomicAdd(d0 + 1, C[mi][nb][1] + b1v);
            float* d1 = dst + (size_t)sm->colI[r + 8] * 128 + c;
            atomicAdd(d1,     C[mi][nb][2] + b0);
            atomicAdd(d1 + 1, C[mi][nb][3] + b1v);
        }
}

// ---- prep kernels ----
__global__ void wprep(const float* __restrict__ w, bf16* __restrict__ dh,
                      bf16* __restrict__ dl, int K) {
    int idx = blockIdx.x * blockDim.x + threadIdx.x;
    if (idx >= K * 128) return;
    int n = idx & 127, k = idx >> 7;
    float v = w[(size_t)k * 128 + n];
    bf16 h = __float2bfloat16_rn(v);
    dh[(size_t)n * K + k] = h;
    dl[(size_t)n * K + k] = __float2bfloat16_rn(v - __bfloat162float(h));
}

__global__ void zero_kernel(float* __restrict__ x2out) {
    size_t n = (size_t)NN * 128;
    for (size_t i = (size_t)blockIdx.x * blockDim.x + threadIdx.x; i < n;
         i += (size_t)gridDim.x * blockDim.x) {
        g_x1[i] = 0.f;
        x2out[i] = 0.f;
    }
}

// ---- Phase A ----
__global__ void __launch_bounds__(NTH, 1)
phaseA(const float* __restrict__ x, const float* __restrict__ ea,
       const int* __restrict__ row, const int* __restrict__ col,
       const float* __restrict__ e1b1, const float* __restrict__ e1b2,
       const float* __restrict__ n1b1, const float* __restrict__ n1b2)
{
    extern __shared__ char raw[];
    SM* sm = (SM*)raw;
    const int tid = threadIdx.x;
    const int e0 = blockIdx.x * TILE;

    if (tid < TILE) sm->rowI[tid] = row[e0 + tid];
    else if (tid < 2 * TILE) sm->colI[tid - TILE] = col[e0 + tid - TILE];
    __syncthreads();

    for (int i = tid; i < TILE * 32; i += NTH) {
        int e = i >> 5, c = (i & 31) * 4;
        float4 v = *(const float4*)&x[(size_t)sm->rowI[e] * 128 + c];
        store_split4(&sm->Ah[e * SA + c], &sm->Al[e * SA + c], v);
    }
    for (int i = tid; i < TILE * 32; i += NTH) {
        int e = i >> 5, c = (i & 31) * 4;
        float4 v = *(const float4*)&x[(size_t)sm->colI[e] * 128 + c];
        store_split4(&sm->Ah[e * SA + 128 + c], &sm->Al[e * SA + 128 + c], v);
    }
    for (int i = tid; i < TILE * 32; i += NTH) {
        int e = i >> 5, c = (i & 31) * 4;
        float4 v = *(const float4*)&ea[(size_t)(e0 + e) * 128 + c];
        store_split4(&sm->Ah[e * SA + 256 + c], &sm->Al[e * SA + 256 + c], v);
    }

    float C[2][4][4];
    // MLP1
    run_gemm(sm, 0, 384, g_wh + W_E1W1, g_wl + W_E1W1, e1b1, sm->b1, C);
    __syncthreads();
    hidden_epilogue(sm, C);
    run_gemm(sm, 256, 128, g_wh + W_E1W2, g_wl + W_E1W2, e1b2, sm->b2, C);
    {   // e1 -> smem cols [128,256)  (disjoint from layer2 reads at [256,384))
        const int lane = tid & 31, wid = tid >> 5;
        const int wM = wid >> 2, wN = wid & 3, g = lane >> 2, q = (lane & 3) * 2;
#pragma unroll
        for (int mi = 0; mi < 2; mi++)
#pragma unroll
            for (int nb = 0; nb < 4; nb++) {
                int r = wM * 32 + mi * 16 + g, c = wN * 32 + nb * 8 + q;
                float b0 = sm->b2[c], b1v = sm->b2[c + 1];
                store_h2(&sm->Ah[r * SA + 128 + c], &sm->Al[r * SA + 128 + c],
                         C[mi][nb][0] + b0, C[mi][nb][1] + b1v);
                store_h2(&sm->Ah[(r + 8) * SA + 128 + c], &sm->Al[(r + 8) * SA + 128 + c],
                         C[mi][nb][2] + b0, C[mi][nb][3] + b1v);
            }
    }
    __syncthreads();
    for (int i = tid; i < TILE * 16; i += NTH) {
        int e = i >> 4, s = (i & 15) * 8;
        *(uint4*)&g_e1h[(size_t)(e0 + e) * 128 + s] = *(const uint4*)&sm->Ah[e * SA + 128 + s];
        *(uint4*)&g_e1l[(size_t)(e0 + e) * 128 + s] = *(const uint4*)&sm->Al[e * SA + 128 + s];
    }
    // MLP2 (input cols [0,256) = [x[row], e1])
    run_gemm(sm, 0, 256, g_wh + W_N1W1, g_wl + W_N1W1, n1b1, sm->b1, C);
    __syncthreads();
    hidden_epilogue(sm, C);
    run_gemm(sm, 256, 128, g_wh + W_N1W2, g_wl + W_N1W2, n1b2, sm->b2, C);
    scatter_epilogue(sm, C, g_x1);
}

// ---- Phase B ----
__global__ void __launch_bounds__(NTH, 1)
phaseB(const int* __restrict__ row, const int* __restrict__ col,
       const float* __restrict__ n2b1, const float* __restrict__ n2b2,
       float* __restrict__ x2out)
{
    extern __shared__ char raw[];
    SM* sm = (SM*)raw;
    const int tid = threadIdx.x;
    const int e0 = blockIdx.x * TILE;

    if (tid < TILE) sm->rowI[tid] = row[e0 + tid];
    else if (tid < 2 * TILE) sm->colI[tid - TILE] = col[e0 + tid - TILE];
    __syncthreads();

    for (int i = tid; i < TILE * 32; i += NTH) {
        int e = i >> 5, c = (i & 31) * 4;
        float4 v = *(const float4*)&g_x1[(size_t)sm->rowI[e] * 128 + c];
        store_split4(&sm->Ah[e * SA + c], &sm->Al[e * SA + c], v);
    }
    for (int i = tid; i < TILE * 16; i += NTH) {
        int e = i >> 4, s = (i & 15) * 8;
        *(uint4*)&sm->Ah[e * SA + 128 + s] = *(const uint4*)&g_e1h[(size_t)(e0 + e) * 128 + s];
        *(uint4*)&sm->Al[e * SA + 128 + s] = *(const uint4*)&g_e1l[(size_t)(e0 + e) * 128 + s];
    }

    float C[2][4][4];
    run_gemm(sm, 0, 256, g_wh + W_N2W1, g_wl + W_N2W1, n2b1, sm->b1, C);
    __syncthreads();
    hidden_epilogue(sm, C);
    run_gemm(sm, 256, 128, g_wh + W_N2W2, g_wl + W_N2W2, n2b2, sm->b2, C);
    scatter_epilogue(sm, C, x2out);
}

// ---- Phase C ----
__global__ void __launch_bounds__(NTH, 1)
phaseC(const int* __restrict__ row, const int* __restrict__ col,
       const float* __restrict__ e2b1, const float* __restrict__ e2b2,
       const float* __restrict__ x2in, float* __restrict__ e2out)
{
    extern __shared__ char raw[];
    SM* sm = (SM*)raw;
    const int tid = threadIdx.x;
    const int e0 = blockIdx.x * TILE;

    if (tid < TILE) sm->rowI[tid] = row[e0 + tid];
    else if (tid < 2 * TILE) sm->colI[tid - TILE] = col[e0 + tid - TILE];
    __syncthreads();

    for (int i = tid; i < TILE * 32; i += NTH) {
        int e = i >> 5, c = (i & 31) * 4;
        float4 v = *(const float4*)&x2in[(size_t)sm->rowI[e] * 128 + c];
        store_split4(&sm->Ah[e * SA + c], &sm->Al[e * SA + c], v);
    }
    for (int i = tid; i < TILE * 32; i += NTH) {
        int e = i >> 5, c = (i & 31) * 4;
        float4 v = *(const float4*)&x2in[(size_t)sm->colI[e] * 128 + c];
        store_split4(&sm->Ah[e * SA + 128 + c], &sm->Al[e * SA + 128 + c], v);
    }
    for (int i = tid; i < TILE * 16; i += NTH) {
        int e = i >> 4, s = (i & 15) * 8;
        *(uint4*)&sm->Ah[e * SA + 256 + s] = *(const uint4*)&g_e1h[(size_t)(e0 + e) * 128 + s];
        *(uint4*)&sm->Al[e * SA + 256 + s] = *(const uint4*)&g_e1l[(size_t)(e0 + e) * 128 + s];
    }

    float C[2][4][4];
    run_gemm(sm, 0, 384, g_wh + W_E2W1, g_wl + W_E2W1, e2b1, sm->b1, C);
    __syncthreads();
    hidden_epilogue(sm, C);
    run_gemm(sm, 256, 128, g_wh + W_E2W2, g_wl + W_E2W2, e2b2, sm->b2, C);
    __syncthreads();   // all layer2 reads done before reusing smem as fp32 staging

    float* sE = (float*)sm->Ah;   // 32 KB fp32 tile fits in Ah region
    {
        const int lane = tid & 31, wid = tid >> 5;
        const int wM = wid >> 2, wN = wid & 3, g = lane >> 2, q = (lane & 3) * 2;
#pragma unroll
        for (int mi = 0; mi < 2; mi++)
#pragma unroll
            for (int nb = 0; nb < 4; nb++) {
                int r = wM * 32 + mi * 16 + g, c = wN * 32 + nb * 8 + q;
                float b0 = sm->b2[c], b1v = sm->b2[c + 1];
                sE[r * 128 + c]       = C[mi][nb][0] + b0;
                sE[r * 128 + c + 1]   = C[mi][nb][1] + b1v;
                sE[(r + 8) * 128 + c]     = C[mi][nb][2] + b0;
                sE[(r + 8) * 128 + c + 1] = C[mi][nb][3] + b1v;
            }
    }
    __syncthreads();
    for (int i = tid; i < TILE * 32; i += NTH) {
        int e = i >> 5, s = (i & 31) * 4;
        *(float4*)&e2out[(size_t)(e0 + e) * 128 + s] = *(const float4*)&sE[e * 128 + s];
    }
}

extern "C" void kernel_launch(void* const* d_in, const int* in_sizes, int n_in,
                              void* d_out, int out_size)
{
    const float* x    = (const float*)d_in[0];
    const float* ea   = (const float*)d_in[1];
    const int*   ei   = (const int*)d_in[2];
    const float* e1w1 = (const float*)d_in[3];
    const float* e1b1 = (const float*)d_in[4];
    const float* e1w2 = (const float*)d_in[5];
    const float* e1b2 = (const float*)d_in[6];
    const float* n1w1 = (const float*)d_in[7];
    const float* n1b1 = (const float*)d_in[8];
    const float* n1w2 = (const float*)d_in[9];
    const float* n1b2 = (const float*)d_in[10];
    const float* n2w1 = (const float*)d_in[11];
    const float* n2b1 = (const float*)d_in[12];
    const float* n2w2 = (const float*)d_in[13];
    const float* n2b2 = (const float*)d_in[14];
    const float* e2w1 = (const float*)d_in[15];
    const float* e2b1 = (const float*)d_in[16];
    const float* e2w2 = (const float*)d_in[17];
    const float* e2b2 = (const float*)d_in[18];

    const int* row = ei;
    const int* col = ei + NE;

    float* out = (float*)d_out;
    float* x2  = out;
    float* e2o = out + (size_t)NN * 128;

    // resolve device-global scratch addresses
    bf16 *wh, *wl;
    cudaGetSymbolAddress((void**)&wh, g_wh);
    cudaGetSymbolAddress((void**)&wl, g_wl);

    // pre-split + transpose weights (tiny)
    wprep<<<(384*128 + 255)/256, 256>>>(e1w1, wh + W_E1W1, wl + W_E1W1, 384);
    wprep<<<(128*128 + 255)/256, 256>>>(e1w2, wh + W_E1W2, wl + W_E1W2, 128);
    wprep<<<(256*128 + 255)/256, 256>>>(n1w1, wh + W_N1W1, wl + W_N1W1, 256);
    wprep<<<(128*128 + 255)/256, 256>>>(n1w2, wh + W_N1W2, wl + W_N1W2, 128);
    wprep<<<(256*128 + 255)/256, 256>>>(n2w1, wh + W_N2W1, wl + W_N2W1, 256);
    wprep<<<(128*128 + 255)/256, 256>>>(n2w2, wh + W_N2W2, wl + W_N2W2, 128);
    wprep<<<(384*128 + 255)/256, 256>>>(e2w1, wh + W_E2W1, wl + W_E2W1, 384);
    wprep<<<(128*128 + 255)/256, 256>>>(e2w2, wh + W_E2W2, wl + W_E2W2, 128);

    zero_kernel<<<512, NTH>>>(x2);

    int smemBytes = (int)sizeof(SM);
    cudaFuncSetAttribute(phaseA, cudaFuncAttributeMaxDynamicSharedMemorySize, smemBytes);
    cudaFuncSetAttribute(phaseB, cudaFuncAttributeMaxDynamicSharedMemorySize, smemBytes);
    cudaFuncSetAttribute(phaseC, cudaFuncAttributeMaxDynamicSharedMemorySize, smemBytes);

    phaseA<<<NE / TILE, NTH, smemBytes>>>(x, ea, row, col, e1b1, e1b2, n1b1, n1b2);
    phaseB<<<NE / TILE, NTH, smemBytes>>>(row, col, n2b1, n2b2, x2);
    phaseC<<<NE / TILE, NTH, smemBytes>>>(row, col, e2b1, e2b2, x2, e2o);
}

// round 3
// speedup vs baseline: 3.0169x; 1.3928x over previous
#include <cuda_runtime.h>
#include <cuda_bf16.h>
#include <cstdint>

#define NN 40000
#define NE 640000
#define TILE 64
#define NTH 256
#define SA 392   // A-plane smem stride (halves): 784B -> %128==16, ldmatrix conflict-free
#define SW 72    // W-plane smem stride (halves): 144B -> %128==16, conflict-free

typedef __nv_bfloat16 bf16;
typedef unsigned int u32;

// ---- device scratch (no allocations allowed) ----
__device__ bf16  g_e1h[(size_t)NE * 128];
__device__ bf16  g_e1l[(size_t)NE * 128];
__device__ float g_x1[(size_t)NN * 128];
__device__ bf16  g_wh[229376];   // all 8 weight mats, transposed [n][k], hi plane
__device__ bf16  g_wl[229376];   // lo plane

// offsets (elements) into g_wh/g_wl: order e1w1,e1w2,n1w1,n1w2,n2w1,n2w2,e2w1,e2w2
#define W_E1W1 0
#define W_E1W2 49152
#define W_N1W1 65536
#define W_N1W2 98304
#define W_N2W1 114688
#define W_N2W2 147456
#define W_E2W1 163840
#define W_E2W2 212992

struct SM {
    bf16 Ah[TILE * SA];     // 50176 B
    bf16 Al[TILE * SA];     // 50176 B
    bf16 Wh[2][128 * SW];   // 2 x 18432 B (double buffer)
    bf16 Wl[2][128 * SW];   // 2 x 18432 B
    float b1[128];
    float b2[128];
    int rowI[TILE];
    int colI[TILE];
};                          // ~175.6 KB

// ---- helpers ----
__device__ __forceinline__ u32 cvta(const void* p) {
    return (u32)__cvta_generic_to_shared(p);
}

__device__ __forceinline__ void cpasync16(u32 dst, const void* src) {
    asm volatile("cp.async.cg.shared.global [%0], [%1], 16;" :: "r"(dst), "l"(src) : "memory");
}
__device__ __forceinline__ void cp_commit() {
    asm volatile("cp.async.commit_group;" ::: "memory");
}
__device__ __forceinline__ void cp_wait0() {
    asm volatile("cp.async.wait_group 0;" ::: "memory");
}

__device__ __forceinline__ void ldsm4(u32 addr, u32& r0, u32& r1, u32& r2, u32& r3) {
    asm volatile("ldmatrix.sync.aligned.m8n8.x4.shared.b16 {%0,%1,%2,%3}, [%4];"
                 : "=r"(r0), "=r"(r1), "=r"(r2), "=r"(r3) : "r"(addr));
}

__device__ __forceinline__ void mma16816(float* c, const u32* a, const u32* b) {
    asm volatile("mma.sync.aligned.m16n8k16.row.col.f32.bf16.bf16.f32 "
                 "{%0,%1,%2,%3}, {%4,%5,%6,%7}, {%8,%9}, {%0,%1,%2,%3};"
                 : "+f"(c[0]), "+f"(c[1]), "+f"(c[2]), "+f"(c[3])
                 : "r"(a[0]), "r"(a[1]), "r"(a[2]), "r"(a[3]), "r"(b[0]), "r"(b[1]));
}

__device__ __forceinline__ void split2(float x, bf16& h, bf16& l) {
    h = __float2bfloat16_rn(x);
    l = __float2bfloat16_rn(x - __bfloat162float(h));
}

__device__ __forceinline__ void store_split4(bf16* ph, bf16* pl, float4 v) {
    bf16 h0,l0,h1,l1,h2,l2,h3,l3;
    split2(v.x,h0,l0); split2(v.y,h1,l1); split2(v.z,h2,l2); split2(v.w,h3,l3);
    __nv_bfloat162 t;
    t.x=h0; t.y=h1; ((__nv_bfloat162*)ph)[0]=t;
    t.x=h2; t.y=h3; ((__nv_bfloat162*)ph)[1]=t;
    t.x=l0; t.y=l1; ((__nv_bfloat162*)pl)[0]=t;
    t.x=l2; t.y=l3; ((__nv_bfloat162*)pl)[1]=t;
}

__device__ __forceinline__ void store_h2(bf16* ph, bf16* pl, float x0, float x1) {
    bf16 h0,l0,h1,l1; split2(x0,h0,l0); split2(x1,h1,l1);
    __nv_bfloat162 t;
    t.x=h0; t.y=h1; *(__nv_bfloat162*)ph = t;
    t.x=l0; t.y=l1; *(__nv_bfloat162*)pl = t;
}

// async-stage one 64-k chunk of both weight planes into buffer `buf`
__device__ __forceinline__ void stage_w(SM* sm, int buf,
    const bf16* __restrict__ gwh, const bf16* __restrict__ gwl, int K, int k0)
{
    u32 dh = cvta(&sm->Wh[buf][0]);
    u32 dl = cvta(&sm->Wl[buf][0]);
    for (int i = threadIdx.x; i < 1024; i += NTH) {
        int r = i >> 3, s = (i & 7) << 3;           // s: halves, 16B granules
        u32 off = (u32)((r * SW + s) * 2);
        const size_t g = (size_t)r * K + k0 + s;
        cpasync16(dh + off, gwh + g);
        cpasync16(dl + off, gwl + g);
    }
}

// GEMM: C[64 x 128] += A(smem planes, cols [aCol, aCol+K)) x W^T(global split, double-buffered)
__device__ __forceinline__ void run_gemm(SM* sm, int aCol, int K,
    const bf16* __restrict__ gwh, const bf16* __restrict__ gwl,
    const float* __restrict__ bias, float* sBias, float C[2][4][4])
{
    const int tid = threadIdx.x, lane = tid & 31, wid = tid >> 5;
    const int wM = wid >> 2, wN = wid & 3;
#pragma unroll
    for (int i = 0; i < 2; i++)
#pragma unroll
        for (int j = 0; j < 4; j++)
#pragma unroll
            for (int q = 0; q < 4; q++) C[i][j][q] = 0.f;

    const u32 ah_base = cvta(sm->Ah), al_base = cvta(sm->Al);
    const u32 wh_base[2] = { cvta(&sm->Wh[0][0]), cvta(&sm->Wh[1][0]) };
    const u32 wl_base[2] = { cvta(&sm->Wl[0][0]), cvta(&sm->Wl[1][0]) };

    const int aRow0 = wM * 32 + (lane & 15);
    const int aColL = (lane >> 4) * 8;
    const int bRowL = (lane & 7) + ((lane & 16) >> 1);
    const int bColL = (lane & 8);

    // preload chunk 0 + bias
    stage_w(sm, 0, gwh, gwl, K, 0);
    if (tid < 128) sBias[tid] = bias[tid];
    cp_commit();

    const int nchunk = K >> 6;
    for (int c = 0; c < nchunk; c++) {
        cp_wait0();          // chunk c resident (this thread's groups)
        __syncthreads();     // visible to all; all readers done with buffer we stage next
        if (c + 1 < nchunk) {
            stage_w(sm, (c + 1) & 1, gwh, gwl, K, (c + 1) << 6);
            cp_commit();
        }
        const int buf = c & 1;
        const int k0 = c << 6;
#pragma unroll
        for (int kk = 0; kk < 64; kk += 16) {
            u32 a_h[2][4], a_l[2][4];
#pragma unroll
            for (int mi = 0; mi < 2; mi++) {
                u32 off = (u32)(((aRow0 + mi * 16) * SA + aCol + k0 + kk + aColL) * 2);
                ldsm4(ah_base + off, a_h[mi][0], a_h[mi][1], a_h[mi][2], a_h[mi][3]);
                ldsm4(al_base + off, a_l[mi][0], a_l[mi][1], a_l[mi][2], a_l[mi][3]);
            }
            u32 b_h[4][2], b_l[4][2];
#pragma unroll
            for (int pr = 0; pr < 2; pr++) {
                u32 off = (u32)(((wN * 32 + pr * 16 + bRowL) * SW + kk + bColL) * 2);
                ldsm4(wh_base[buf] + off, b_h[2*pr][0], b_h[2*pr][1], b_h[2*pr+1][0], b_h[2*pr+1][1]);
                ldsm4(wl_base[buf] + off, b_l[2*pr][0], b_l[2*pr][1], b_l[2*pr+1][0], b_l[2*pr+1][1]);
            }
#pragma unroll
            for (int mi = 0; mi < 2; mi++)
#pragma unroll
                for (int nb = 0; nb < 4; nb++) {
                    mma16816(C[mi][nb], a_h[mi], b_h[nb]);
                    mma16816(C[mi][nb], a_l[mi], b_h[nb]);
                    mma16816(C[mi][nb], a_h[mi], b_l[nb]);
                }
        }
    }
}

// hidden = relu(C + b1) -> split -> smem cols [256,384)
__device__ __forceinline__ void hidden_epilogue(SM* sm, float C[2][4][4]) {
    const int lane = threadIdx.x & 31, wid = threadIdx.x >> 5;
    const int wM = wid >> 2, wN = wid & 3, g = lane >> 2, q = (lane & 3) * 2;
#pragma unroll
    for (int mi = 0; mi < 2; mi++)
#pragma unroll
        for (int nb = 0; nb < 4; nb++) {
            int r = wM * 32 + mi * 16 + g, c = wN * 32 + nb * 8 + q;
            float b0 = sm->b1[c], b1v = sm->b1[c + 1];
            store_h2(&sm->Ah[r * SA + 256 + c], &sm->Al[r * SA + 256 + c],
                     fmaxf(C[mi][nb][0] + b0, 0.f), fmaxf(C[mi][nb][1] + b1v, 0.f));
            store_h2(&sm->Ah[(r + 8) * SA + 256 + c], &sm->Al[(r + 8) * SA + 256 + c],
                     fmaxf(C[mi][nb][2] + b0, 0.f), fmaxf(C[mi][nb][3] + b1v, 0.f));
        }
}

__device__ __forceinline__ void scatter_epilogue(SM* sm, float C[2][4][4], float* __restrict__ dst) {
    const int lane = threadIdx.x & 31, wid = threadIdx.x >> 5;
    const int wM = wid >> 2, wN = wid & 3, g = lane >> 2, q = (lane & 3) * 2;
#pragma unroll
    for (int mi = 0; mi < 2; mi++)
#pragma unroll
        for (int nb = 0; nb < 4; nb++) {
            int r = wM * 32 + mi * 16 + g, c = wN * 32 + nb * 8 + q;
            float b0 = sm->b2[c], b1v = sm->b2[c + 1];
            float* d0 = dst + (size_t)sm->colI[r] * 128 + c;
            atomicAdd(d0,     C[mi][nb][0] + b0);
            atomicAdd(d0 + 1, C[mi][nb][1] + b1v);
            float* d1 = dst + (size_t)sm->colI[r + 8] * 128 + c;
            atomicAdd(d1,     C[mi][nb][2] + b0);
            atomicAdd(d1 + 1, C[mi][nb][3] + b1v);
        }
}

// ---- prep kernels ----
__global__ void wprep_all(const float* __restrict__ w0, const float* __restrict__ w1,
                          const float* __restrict__ w2, const float* __restrict__ w3,
                          const float* __restrict__ w4, const float* __restrict__ w5,
                          const float* __restrict__ w6, const float* __restrict__ w7,
                          bf16* __restrict__ dh, bf16* __restrict__ dl)
{
    const int offs[9] = {0, 49152, 65536, 98304, 114688, 147456, 163840, 212992, 229376};
    const int Ks[8]   = {384, 128, 256, 128, 256, 128, 384, 128};
    const float* ws[8] = {w0, w1, w2, w3, w4, w5, w6, w7};
    int idx = blockIdx.x * blockDim.x + threadIdx.x;
    if (idx >= 229376) return;
    int m = 0;
    while (idx >= offs[m + 1]) m++;
    int local = idx - offs[m];
    int K = Ks[m];
    int n = local / K;
    int k = local - n * K;
    float v = ws[m][(size_t)k * 128 + n];
    bf16 h = __float2bfloat16_rn(v);
    dh[idx] = h;
    dl[idx] = __float2bfloat16_rn(v - __bfloat162float(h));
}

__global__ void zero_kernel(float* __restrict__ x2out) {
    size_t n = (size_t)NN * 128;
    for (size_t i = (size_t)blockIdx.x * blockDim.x + threadIdx.x; i < n;
         i += (size_t)gridDim.x * blockDim.x) {
        g_x1[i] = 0.f;
        x2out[i] = 0.f;
    }
}

// ---- Phase A ----
__global__ void __launch_bounds__(NTH, 1)
phaseA(const float* __restrict__ x, const float* __restrict__ ea,
       const int* __restrict__ row, const int* __restrict__ col,
       const float* __restrict__ e1b1, const float* __restrict__ e1b2,
       const float* __restrict__ n1b1, const float* __restrict__ n1b2)
{
    extern __shared__ char raw[];
    SM* sm = (SM*)raw;
    const int tid = threadIdx.x;
    const int e0 = blockIdx.x * TILE;

    if (tid < TILE) sm->rowI[tid] = row[e0 + tid];
    else if (tid < 2 * TILE) sm->colI[tid - TILE] = col[e0 + tid - TILE];
    __syncthreads();

    for (int i = tid; i < TILE * 32; i += NTH) {
        int e = i >> 5, c = (i & 31) * 4;
        float4 v = *(const float4*)&x[(size_t)sm->rowI[e] * 128 + c];
        store_split4(&sm->Ah[e * SA + c], &sm->Al[e * SA + c], v);
    }
    for (int i = tid; i < TILE * 32; i += NTH) {
        int e = i >> 5, c = (i & 31) * 4;
        float4 v = *(const float4*)&x[(size_t)sm->colI[e] * 128 + c];
        store_split4(&sm->Ah[e * SA + 128 + c], &sm->Al[e * SA + 128 + c], v);
    }
    for (int i = tid; i < TILE * 32; i += NTH) {
        int e = i >> 5, c = (i & 31) * 4;
        float4 v = *(const float4*)&ea[(size_t)(e0 + e) * 128 + c];
        store_split4(&sm->Ah[e * SA + 256 + c], &sm->Al[e * SA + 256 + c], v);
    }

    float C[2][4][4];
    // MLP1
    run_gemm(sm, 0, 384, g_wh + W_E1W1, g_wl + W_E1W1, e1b1, sm->b1, C);
    __syncthreads();
    hidden_epilogue(sm, C);
    run_gemm(sm, 256, 128, g_wh + W_E1W2, g_wl + W_E1W2, e1b2, sm->b2, C);
    {   // e1 -> smem cols [128,256)  (disjoint from layer2 reads at [256,384))
        const int lane = tid & 31, wid = tid >> 5;
        const int wM = wid >> 2, wN = wid & 3, g = lane >> 2, q = (lane & 3) * 2;
#pragma unroll
        for (int mi = 0; mi < 2; mi++)
#pragma unroll
            for (int nb = 0; nb < 4; nb++) {
                int r = wM * 32 + mi * 16 + g, c = wN * 32 + nb * 8 + q;
                float b0 = sm->b2[c], b1v = sm->b2[c + 1];
                store_h2(&sm->Ah[r * SA + 128 + c], &sm->Al[r * SA + 128 + c],
                         C[mi][nb][0] + b0, C[mi][nb][1] + b1v);
                store_h2(&sm->Ah[(r + 8) * SA + 128 + c], &sm->Al[(r + 8) * SA + 128 + c],
                         C[mi][nb][2] + b0, C[mi][nb][3] + b1v);
            }
    }
    __syncthreads();
    for (int i = tid; i < TILE * 16; i += NTH) {
        int e = i >> 4, s = (i & 15) * 8;
        *(uint4*)&g_e1h[(size_t)(e0 + e) * 128 + s] = *(const uint4*)&sm->Ah[e * SA + 128 + s];
        *(uint4*)&g_e1l[(size_t)(e0 + e) * 128 + s] = *(const uint4*)&sm->Al[e * SA + 128 + s];
    }
    // MLP2 (input cols [0,256) = [x[row], e1])
    run_gemm(sm, 0, 256, g_wh + W_N1W1, g_wl + W_N1W1, n1b1, sm->b1, C);
    __syncthreads();
    hidden_epilogue(sm, C);
    run_gemm(sm, 256, 128, g_wh + W_N1W2, g_wl + W_N1W2, n1b2, sm->b2, C);
    scatter_epilogue(sm, C, g_x1);
}

// ---- Phase B ----
__global__ void __launch_bounds__(NTH, 1)
phaseB(const int* __restrict__ row, const int* __restrict__ col,
       const float* __restrict__ n2b1, const float* __restrict__ n2b2,
       float* __restrict__ x2out)
{
    extern __shared__ char raw[];
    SM* sm = (SM*)raw;
    const int tid = threadIdx.x;
    const int e0 = blockIdx.x * TILE;

    if (tid < TILE) sm->rowI[tid] = row[e0 + tid];
    else if (tid < 2 * TILE) sm->colI[tid - TILE] = col[e0 + tid - TILE];
    __syncthreads();

    // e1 planes: direct async copy (completes at first gemm wait)
    {
        u32 ah = cvta(sm->Ah), al = cvta(sm->Al);
        for (int i = tid; i < TILE * 16; i += NTH) {
            int e = i >> 4, s = (i & 15) * 8;
            u32 off = (u32)((e * SA + 128 + s) * 2);
            cpasync16(ah + off, &g_e1h[(size_t)(e0 + e) * 128 + s]);
            cpasync16(al + off, &g_e1l[(size_t)(e0 + e) * 128 + s]);
        }
    }
    for (int i = tid; i < TILE * 32; i += NTH) {
        int e = i >> 5, c = (i & 31) * 4;
        float4 v = *(const float4*)&g_x1[(size_t)sm->rowI[e] * 128 + c];
        store_split4(&sm->Ah[e * SA + c], &sm->Al[e * SA + c], v);
    }

    float C[2][4][4];
    run_gemm(sm, 0, 256, g_wh + W_N2W1, g_wl + W_N2W1, n2b1, sm->b1, C);
    __syncthreads();
    hidden_epilogue(sm, C);
    run_gemm(sm, 256, 128, g_wh + W_N2W2, g_wl + W_N2W2, n2b2, sm->b2, C);
    scatter_epilogue(sm, C, x2out);
}

// ---- Phase C ----
__global__ void __launch_bounds__(NTH, 1)
phaseC(const int* __restrict__ row, const int* __restrict__ col,
       const float* __restrict__ e2b1, const float* __restrict__ e2b2,
       const float* __restrict__ x2in, float* __restrict__ e2out)
{
    extern __shared__ char raw[];
    SM* sm = (SM*)raw;
    const int tid = threadIdx.x;
    const int e0 = blockIdx.x * TILE;

    if (tid < TILE) sm->rowI[tid] = row[e0 + tid];
    else if (tid < 2 * TILE) sm->colI[tid - TILE] = col[e0 + tid - TILE];
    __syncthreads();

    {
        u32 ah = cvta(sm->Ah), al = cvta(sm->Al);
        for (int i = tid; i < TILE * 16; i += NTH) {
            int e = i >> 4, s = (i & 15) * 8;
            u32 off = (u32)((e * SA + 256 + s) * 2);
            cpasync16(ah + off, &g_e1h[(size_t)(e0 + e) * 128 + s]);
            cpasync16(al + off, &g_e1l[(size_t)(e0 + e) * 128 + s]);
        }
    }
    for (int i = tid; i < TILE * 32; i += NTH) {
        int e = i >> 5, c = (i & 31) * 4;
        float4 v = *(const float4*)&x2in[(size_t)sm->rowI[e] * 128 + c];
        store_split4(&sm->Ah[e * SA + c], &sm->Al[e * SA + c], v);
    }
    for (int i = tid; i < TILE * 32; i += NTH) {
        int e = i >> 5, c = (i & 31) * 4;
        float4 v = *(const float4*)&x2in[(size_t)sm->colI[e] * 128 + c];
        store_split4(&sm->Ah[e * SA + 128 + c], &sm->Al[e * SA + 128 + c], v);
    }

    float C[2][4][4];
    run_gemm(sm, 0, 384, g_wh + W_E2W1, g_wl + W_E2W1, e2b1, sm->b1, C);
    __syncthreads();
    hidden_epilogue(sm, C);
    run_gemm(sm, 256, 128, g_wh + W_E2W2, g_wl + W_E2W2, e2b2, sm->b2, C);
    __syncthreads();   // all layer2 reads done before reusing smem as fp32 staging

    float* sE = (float*)sm->Ah;   // 32 KB fp32 tile fits in Ah region
    {
        const int lane = tid & 31, wid = tid >> 5;
        const int wM = wid >> 2, wN = wid & 3, g = lane >> 2, q = (lane & 3) * 2;
#pragma unroll
        for (int mi = 0; mi < 2; mi++)
#pragma unroll
            for (int nb = 0; nb < 4; nb++) {
                int r = wM * 32 + mi * 16 + g, c = wN * 32 + nb * 8 + q;
                float b0 = sm->b2[c], b1v = sm->b2[c + 1];
                sE[r * 128 + c]           = C[mi][nb][0] + b0;
                sE[r * 128 + c + 1]       = C[mi][nb][1] + b1v;
                sE[(r + 8) * 128 + c]     = C[mi][nb][2] + b0;
                sE[(r + 8) * 128 + c + 1] = C[mi][nb][3] + b1v;
            }
    }
    __syncthreads();
    for (int i = tid; i < TILE * 32; i += NTH) {
        int e = i >> 5, s = (i & 31) * 4;
        *(float4*)&e2out[(size_t)(e0 + e) * 128 + s] = *(const float4*)&sE[e * 128 + s];
    }
}

extern "C" void kernel_launch(void* const* d_in, const int* in_sizes, int n_in,
                              void* d_out, int out_size)
{
    const float* x    = (const float*)d_in[0];
    const float* ea   = (const float*)d_in[1];
    const int*   ei   = (const int*)d_in[2];
    const float* e1w1 = (const float*)d_in[3];
    const float* e1b1 = (const float*)d_in[4];
    const float* e1w2 = (const float*)d_in[5];
    const float* e1b2 = (const float*)d_in[6];
    const float* n1w1 = (const float*)d_in[7];
    const float* n1b1 = (const float*)d_in[8];
    const float* n1w2 = (const float*)d_in[9];
    const float* n1b2 = (const float*)d_in[10];
    const float* n2w1 = (const float*)d_in[11];
    const float* n2b1 = (const float*)d_in[12];
    const float* n2w2 = (const float*)d_in[13];
    const float* n2b2 = (const float*)d_in[14];
    const float* e2w1 = (const float*)d_in[15];
    const float* e2b1 = (const float*)d_in[16];
    const float* e2w2 = (const float*)d_in[17];
    const float* e2b2 = (const float*)d_in[18];

    const int* row = ei;
    const int* col = ei + NE;

    float* out = (float*)d_out;
    float* x2  = out;
    float* e2o = out + (size_t)NN * 128;

    bf16 *wh, *wl;
    cudaGetSymbolAddress((void**)&wh, g_wh);
    cudaGetSymbolAddress((void**)&wl, g_wl);

    wprep_all<<<(229376 + 255) / 256, 256>>>(e1w1, e1w2, n1w1, n1w2,
                                             n2w1, n2w2, e2w1, e2w2, wh, wl);
    zero_kernel<<<1024, NTH>>>(x2);

    int smemBytes = (int)sizeof(SM);
    cudaFuncSetAttribute(phaseA, cudaFuncAttributeMaxDynamicSharedMemorySize, smemBytes);
    cudaFuncSetAttribute(phaseB, cudaFuncAttributeMaxDynamicSharedMemorySize, smemBytes);
    cudaFuncSetAttribute(phaseC, cudaFuncAttributeMaxDynamicSharedMemorySize, smemBytes);

    phaseA<<<NE / TILE, NTH, smemBytes>>>(x, ea, row, col, e1b1, e1b2, n1b1, n1b2);
    phaseB<<<NE / TILE, NTH, smemBytes>>>(row, col, n2b1, n2b2, x2);
    phaseC<<<NE / TILE, NTH, smemBytes>>>(row, col, e2b1, e2b2, x2, e2o);
}

// round 4
// speedup vs baseline: 3.7908x; 1.2566x over previous
#include <cuda_runtime.h>
#include <cuda_bf16.h>
#include <cstdint>

#define NN 40000
#define NE 640000
#define TILE 64
#define NTH 256
#define SA 392   // A-plane smem stride (halves)
#define SW 72    // W-plane smem stride (halves)

typedef __nv_bfloat16 bf16;
typedef unsigned int u32;

// ---- device scratch ----
__device__ bf16  g_e1h[(size_t)NE * 128];   // holds ea-split before phase A, e1-split after
__device__ bf16  g_e1l[(size_t)NE * 128];
__device__ float g_x1[(size_t)NN * 128];
__device__ bf16  g_xh[(size_t)NN * 128];
__device__ bf16  g_xl[(size_t)NN * 128];
__device__ bf16  g_x1h[(size_t)NN * 128];
__device__ bf16  g_x1l[(size_t)NN * 128];
__device__ bf16  g_x2h[(size_t)NN * 128];
__device__ bf16  g_x2l[(size_t)NN * 128];
__device__ bf16  g_wh[229376];
__device__ bf16  g_wl[229376];

#define W_E1W1 0
#define W_E1W2 49152
#define W_N1W1 65536
#define W_N1W2 98304
#define W_N2W1 114688
#define W_N2W2 147456
#define W_E2W1 163840
#define W_E2W2 212992

struct SM {
    bf16 Ah[TILE * SA];
    bf16 Al[TILE * SA];
    bf16 Wh[2][128 * SW];
    bf16 Wl[2][128 * SW];
    float b1[128];
    float b2[128];
    int rowI[TILE];
    int colI[TILE];
};

// ---- helpers ----
__device__ __forceinline__ u32 cvta(const void* p) {
    return (u32)__cvta_generic_to_shared(p);
}
__device__ __forceinline__ void cpasync16(u32 dst, const void* src) {
    asm volatile("cp.async.cg.shared.global [%0], [%1], 16;" :: "r"(dst), "l"(src) : "memory");
}
__device__ __forceinline__ void cp_commit() {
    asm volatile("cp.async.commit_group;" ::: "memory");
}
__device__ __forceinline__ void cp_wait0() {
    asm volatile("cp.async.wait_group 0;" ::: "memory");
}
__device__ __forceinline__ void ldsm4(u32 addr, u32& r0, u32& r1, u32& r2, u32& r3) {
    asm volatile("ldmatrix.sync.aligned.m8n8.x4.shared.b16 {%0,%1,%2,%3}, [%4];"
                 : "=r"(r0), "=r"(r1), "=r"(r2), "=r"(r3) : "r"(addr));
}
__device__ __forceinline__ void mma16816(float* c, const u32* a, const u32* b) {
    asm volatile("mma.sync.aligned.m16n8k16.row.col.f32.bf16.bf16.f32 "
                 "{%0,%1,%2,%3}, {%4,%5,%6,%7}, {%8,%9}, {%0,%1,%2,%3};"
                 : "+f"(c[0]), "+f"(c[1]), "+f"(c[2]), "+f"(c[3])
                 : "r"(a[0]), "r"(a[1]), "r"(a[2]), "r"(a[3]), "r"(b[0]), "r"(b[1]));
}
__device__ __forceinline__ void red2(float* p, float v0, float v1) {
    asm volatile("red.global.add.v2.f32 [%0], {%1,%2};" :: "l"(p), "f"(v0), "f"(v1) : "memory");
}
__device__ __forceinline__ void split2(float x, bf16& h, bf16& l) {
    h = __float2bfloat16_rn(x);
    l = __float2bfloat16_rn(x - __bfloat162float(h));
}
__device__ __forceinline__ void store_h2(bf16* ph, bf16* pl, float x0, float x1) {
    bf16 h0,l0,h1,l1; split2(x0,h0,l0); split2(x1,h1,l1);
    __nv_bfloat162 t;
    t.x=h0; t.y=h1; *(__nv_bfloat162*)ph = t;
    t.x=l0; t.y=l1; *(__nv_bfloat162*)pl = t;
}

__device__ __forceinline__ void stage_w(SM* sm, int buf,
    const bf16* __restrict__ gwh, const bf16* __restrict__ gwl, int K, int k0)
{
    u32 dh = cvta(&sm->Wh[buf][0]);
    u32 dl = cvta(&sm->Wl[buf][0]);
    for (int i = threadIdx.x; i < 1024; i += NTH) {
        int r = i >> 3, s = (i & 7) << 3;
        u32 off = (u32)((r * SW + s) * 2);
        const size_t g = (size_t)r * K + k0 + s;
        cpasync16(dh + off, gwh + g);
        cpasync16(dl + off, gwl + g);
    }
}

__device__ __forceinline__ void run_gemm(SM* sm, int aCol, int K,
    const bf16* __restrict__ gwh, const bf16* __restrict__ gwl,
    const float* __restrict__ bias, float* sBias, float C[2][4][4])
{
    const int tid = threadIdx.x, lane = tid & 31, wid = tid >> 5;
    const int wM = wid >> 2, wN = wid & 3;
#pragma unroll
    for (int i = 0; i < 2; i++)
#pragma unroll
        for (int j = 0; j < 4; j++)
#pragma unroll
            for (int q = 0; q < 4; q++) C[i][j][q] = 0.f;

    const u32 ah_base = cvta(sm->Ah), al_base = cvta(sm->Al);
    const u32 wh_base[2] = { cvta(&sm->Wh[0][0]), cvta(&sm->Wh[1][0]) };
    const u32 wl_base[2] = { cvta(&sm->Wl[0][0]), cvta(&sm->Wl[1][0]) };

    const int aRow0 = wM * 32 + (lane & 15);
    const int aColL = (lane >> 4) * 8;
    const int bRowL = (lane & 7) + ((lane & 16) >> 1);
    const int bColL = (lane & 8);

    stage_w(sm, 0, gwh, gwl, K, 0);
    if (tid < 128) sBias[tid] = bias[tid];
    cp_commit();

    const int nchunk = K >> 6;
    for (int c = 0; c < nchunk; c++) {
        cp_wait0();
        __syncthreads();
        if (c + 1 < nchunk) {
            stage_w(sm, (c + 1) & 1, gwh, gwl, K, (c + 1) << 6);
            cp_commit();
        }
        const int buf = c & 1;
        const int k0 = c << 6;
#pragma unroll
        for (int kk = 0; kk < 64; kk += 16) {
            u32 a_h[2][4], a_l[2][4];
#pragma unroll
            for (int mi = 0; mi < 2; mi++) {
                u32 off = (u32)(((aRow0 + mi * 16) * SA + aCol + k0 + kk + aColL) * 2);
                ldsm4(ah_base + off, a_h[mi][0], a_h[mi][1], a_h[mi][2], a_h[mi][3]);
                ldsm4(al_base + off, a_l[mi][0], a_l[mi][1], a_l[mi][2], a_l[mi][3]);
            }
            u32 b_h[4][2], b_l[4][2];
#pragma unroll
            for (int pr = 0; pr < 2; pr++) {
                u32 off = (u32)(((wN * 32 + pr * 16 + bRowL) * SW + kk + bColL) * 2);
                ldsm4(wh_base[buf] + off, b_h[2*pr][0], b_h[2*pr][1], b_h[2*pr+1][0], b_h[2*pr+1][1]);
                ldsm4(wl_base[buf] + off, b_l[2*pr][0], b_l[2*pr][1], b_l[2*pr+1][0], b_l[2*pr+1][1]);
            }
#pragma unroll
            for (int mi = 0; mi < 2; mi++)
#pragma unroll
                for (int nb = 0; nb < 4; nb++) {
                    mma16816(C[mi][nb], a_h[mi], b_h[nb]);
                    mma16816(C[mi][nb], a_l[mi], b_h[nb]);
                    mma16816(C[mi][nb], a_h[mi], b_l[nb]);
                }
        }
    }
}

__device__ __forceinline__ void hidden_epilogue(SM* sm, float C[2][4][4]) {
    const int lane = threadIdx.x & 31, wid = threadIdx.x >> 5;
    const int wM = wid >> 2, wN = wid & 3, g = lane >> 2, q = (lane & 3) * 2;
#pragma unroll
    for (int mi = 0; mi < 2; mi++)
#pragma unroll
        for (int nb = 0; nb < 4; nb++) {
            int r = wM * 32 + mi * 16 + g, c = wN * 32 + nb * 8 + q;
            float b0 = sm->b1[c], b1v = sm->b1[c + 1];
            store_h2(&sm->Ah[r * SA + 256 + c], &sm->Al[r * SA + 256 + c],
                     fmaxf(C[mi][nb][0] + b0, 0.f), fmaxf(C[mi][nb][1] + b1v, 0.f));
            store_h2(&sm->Ah[(r + 8) * SA + 256 + c], &sm->Al[(r + 8) * SA + 256 + c],
                     fmaxf(C[mi][nb][2] + b0, 0.f), fmaxf(C[mi][nb][3] + b1v, 0.f));
        }
}

__device__ __forceinline__ void scatter_epilogue(SM* sm, float C[2][4][4], float* __restrict__ dst) {
    const int lane = threadIdx.x & 31, wid = threadIdx.x >> 5;
    const int wM = wid >> 2, wN = wid & 3, g = lane >> 2, q = (lane & 3) * 2;
#pragma unroll
    for (int mi = 0; mi < 2; mi++)
#pragma unroll
        for (int nb = 0; nb < 4; nb++) {
            int r = wM * 32 + mi * 16 + g, c = wN * 32 + nb * 8 + q;
            float b0 = sm->b2[c], b1v = sm->b2[c + 1];
            red2(dst + (size_t)sm->colI[r] * 128 + c,     C[mi][nb][0] + b0, C[mi][nb][1] + b1v);
            red2(dst + (size_t)sm->colI[r + 8] * 128 + c, C[mi][nb][2] + b0, C[mi][nb][3] + b1v);
        }
}

// ---- prep kernels ----
__global__ void wprep_all(const float* __restrict__ w0, const float* __restrict__ w1,
                          const float* __restrict__ w2, const float* __restrict__ w3,
                          const float* __restrict__ w4, const float* __restrict__ w5,
                          const float* __restrict__ w6, const float* __restrict__ w7,
                          bf16* __restrict__ dh, bf16* __restrict__ dl)
{
    const int offs[9] = {0, 49152, 65536, 98304, 114688, 147456, 163840, 212992, 229376};
    const int Ks[8]   = {384, 128, 256, 128, 256, 128, 384, 128};
    const float* ws[8] = {w0, w1, w2, w3, w4, w5, w6, w7};
    int idx = blockIdx.x * blockDim.x + threadIdx.x;
    if (idx >= 229376) return;
    int m = 0;
    while (idx >= offs[m + 1]) m++;
    int local = idx - offs[m];
    int K = Ks[m];
    int n = local / K;
    int k = local - n * K;
    float v = ws[m][(size_t)k * 128 + n];
    bf16 h = __float2bfloat16_rn(v);
    dh[idx] = h;
    dl[idx] = __float2bfloat16_rn(v - __bfloat162float(h));
}

// split fp32 -> bf16 hi/lo planes, n multiple of 4
__global__ void prep_split(const float* __restrict__ src, bf16* __restrict__ dh,
                           bf16* __restrict__ dl, size_t n4)
{
    for (size_t i = (size_t)blockIdx.x * blockDim.x + threadIdx.x; i < n4;
         i += (size_t)gridDim.x * blockDim.x) {
        float4 v = ((const float4*)src)[i];
        bf16 h0,l0,h1,l1,h2,l2,h3,l3;
        split2(v.x,h0,l0); split2(v.y,h1,l1); split2(v.z,h2,l2); split2(v.w,h3,l3);
        __nv_bfloat162 a,b;
        a.x=h0; a.y=h1; b.x=h2; b.y=h3;
        ((__nv_bfloat162*)dh)[i*2] = a; ((__nv_bfloat162*)dh)[i*2+1] = b;
        a.x=l0; a.y=l1; b.x=l2; b.y=l3;
        ((__nv_bfloat162*)dl)[i*2] = a; ((__nv_bfloat162*)dl)[i*2+1] = b;
    }
}

__global__ void zero_kernel(float* __restrict__ x2out) {
    size_t n = (size_t)NN * 128;
    for (size_t i = (size_t)blockIdx.x * blockDim.x + threadIdx.x; i < n;
         i += (size_t)gridDim.x * blockDim.x) {
        g_x1[i] = 0.f;
        x2out[i] = 0.f;
    }
}

// gather one 128-col bf16 row-pair (hi+lo) via cp.async; seg = dest col offset
__device__ __forceinline__ void gather_rows(SM* sm, int seg,
    const bf16* __restrict__ srch, const bf16* __restrict__ srcl, const int* idx, int e0, int useIdx)
{
    u32 ah = cvta(sm->Ah), al = cvta(sm->Al);
    for (int i = threadIdx.x; i < TILE * 16; i += NTH) {
        int e = i >> 4, s = (i & 15) * 8;
        size_t r = useIdx ? (size_t)idx[e] : (size_t)(e0 + e);
        u32 off = (u32)((e * SA + seg + s) * 2);
        cpasync16(ah + off, srch + r * 128 + s);
        cpasync16(al + off, srcl + r * 128 + s);
    }
}

// ---- Phase A ----
__global__ void __launch_bounds__(NTH, 1)
phaseA(const int* __restrict__ row, const int* __restrict__ col,
       const float* __restrict__ e1b1, const float* __restrict__ e1b2,
       const float* __restrict__ n1b1, const float* __restrict__ n1b2)
{
    extern __shared__ char raw[];
    SM* sm = (SM*)raw;
    const int tid = threadIdx.x;
    const int e0 = blockIdx.x * TILE;

    if (tid < TILE) sm->rowI[tid] = row[e0 + tid];
    else if (tid < 2 * TILE) sm->colI[tid - TILE] = col[e0 + tid - TILE];
    __syncthreads();

    gather_rows(sm, 0,   g_xh, g_xl, sm->rowI, e0, 1);
    gather_rows(sm, 128, g_xh, g_xl, sm->colI, e0, 1);
    gather_rows(sm, 256, g_e1h, g_e1l, 0, e0, 0);   // ea-split lives here pre-phase-A

    float C[2][4][4];
    run_gemm(sm, 0, 384, g_wh + W_E1W1, g_wl + W_E1W1, e1b1, sm->b1, C);
    __syncthreads();
    hidden_epilogue(sm, C);
    run_gemm(sm, 256, 128, g_wh + W_E1W2, g_wl + W_E1W2, e1b2, sm->b2, C);
    {   // e1 -> smem cols [128,256)
        const int lane = tid & 31, wid = tid >> 5;
        const int wM = wid >> 2, wN = wid & 3, g = lane >> 2, q = (lane & 3) * 2;
#pragma unroll
        for (int mi = 0; mi < 2; mi++)
#pragma unroll
            for (int nb = 0; nb < 4; nb++) {
                int r = wM * 32 + mi * 16 + g, c = wN * 32 + nb * 8 + q;
                float b0 = sm->b2[c], b1v = sm->b2[c + 1];
                store_h2(&sm->Ah[r * SA + 128 + c], &sm->Al[r * SA + 128 + c],
                         C[mi][nb][0] + b0, C[mi][nb][1] + b1v);
                store_h2(&sm->Ah[(r + 8) * SA + 128 + c], &sm->Al[(r + 8) * SA + 128 + c],
                         C[mi][nb][2] + b0, C[mi][nb][3] + b1v);
            }
    }
    __syncthreads();
    for (int i = tid; i < TILE * 16; i += NTH) {
        int e = i >> 4, s = (i & 15) * 8;
        *(uint4*)&g_e1h[(size_t)(e0 + e) * 128 + s] = *(const uint4*)&sm->Ah[e * SA + 128 + s];
        *(uint4*)&g_e1l[(size_t)(e0 + e) * 128 + s] = *(const uint4*)&sm->Al[e * SA + 128 + s];
    }
    run_gemm(sm, 0, 256, g_wh + W_N1W1, g_wl + W_N1W1, n1b1, sm->b1, C);
    __syncthreads();
    hidden_epilogue(sm, C);
    run_gemm(sm, 256, 128, g_wh + W_N1W2, g_wl + W_N1W2, n1b2, sm->b2, C);
    scatter_epilogue(sm, C, g_x1);
}

// ---- Phase B ----
__global__ void __launch_bounds__(NTH, 1)
phaseB(const int* __restrict__ row, const int* __restrict__ col,
       const float* __restrict__ n2b1, const float* __restrict__ n2b2,
       float* __restrict__ x2out)
{
    extern __shared__ char raw[];
    SM* sm = (SM*)raw;
    const int tid = threadIdx.x;
    const int e0 = blockIdx.x * TILE;

    if (tid < TILE) sm->rowI[tid] = row[e0 + tid];
    else if (tid < 2 * TILE) sm->colI[tid - TILE] = col[e0 + tid - TILE];
    __syncthreads();

    gather_rows(sm, 0,   g_x1h, g_x1l, sm->rowI, e0, 1);
    gather_rows(sm, 128, g_e1h, g_e1l, 0, e0, 0);

    float C[2][4][4];
    run_gemm(sm, 0, 256, g_wh + W_N2W1, g_wl + W_N2W1, n2b1, sm->b1, C);
    __syncthreads();
    hidden_epilogue(sm, C);
    run_gemm(sm, 256, 128, g_wh + W_N2W2, g_wl + W_N2W2, n2b2, sm->b2, C);
    scatter_epilogue(sm, C, x2out);
}

// ---- Phase C ----
__global__ void __launch_bounds__(NTH, 1)
phaseC(const int* __restrict__ row, const int* __restrict__ col,
       const float* __restrict__ e2b1, const float* __restrict__ e2b2,
       float* __restrict__ e2out)
{
    extern __shared__ char raw[];
    SM* sm = (SM*)raw;
    const int tid = threadIdx.x;
    const int e0 = blockIdx.x * TILE;

    if (tid < TILE) sm->rowI[tid] = row[e0 + tid];
    else if (tid < 2 * TILE) sm->colI[tid - TILE] = col[e0 + tid - TILE];
    __syncthreads();

    gather_rows(sm, 0,   g_x2h, g_x2l, sm->rowI, e0, 1);
    gather_rows(sm, 128, g_x2h, g_x2l, sm->colI, e0, 1);
    gather_rows(sm, 256, g_e1h, g_e1l, 0, e0, 0);

    float C[2][4][4];
    run_gemm(sm, 0, 384, g_wh + W_E2W1, g_wl + W_E2W1, e2b1, sm->b1, C);
    __syncthreads();
    hidden_epilogue(sm, C);
    run_gemm(sm, 256, 128, g_wh + W_E2W2, g_wl + W_E2W2, e2b2, sm->b2, C);
    __syncthreads();

    float* sE = (float*)sm->Ah;
    {
        const int lane = tid & 31, wid = tid >> 5;
        const int wM = wid >> 2, wN = wid & 3, g = lane >> 2, q = (lane & 3) * 2;
#pragma unroll
        for (int mi = 0; mi < 2; mi++)
#pragma unroll
            for (int nb = 0; nb < 4; nb++) {
                int r = wM * 32 + mi * 16 + g, c = wN * 32 + nb * 8 + q;
                float b0 = sm->b2[c], b1v = sm->b2[c + 1];
                sE[r * 128 + c]           = C[mi][nb][0] + b0;
                sE[r * 128 + c + 1]       = C[mi][nb][1] + b1v;
                sE[(r + 8) * 128 + c]     = C[mi][nb][2] + b0;
                sE[(r + 8) * 128 + c + 1] = C[mi][nb][3] + b1v;
            }
    }
    __syncthreads();
    for (int i = tid; i < TILE * 32; i += NTH) {
        int e = i >> 5, s = (i & 31) * 4;
        *(float4*)&e2out[(size_t)(e0 + e) * 128 + s] = *(const float4*)&sE[e * 128 + s];
    }
}

extern "C" void kernel_launch(void* const* d_in, const int* in_sizes, int n_in,
                              void* d_out, int out_size)
{
    const float* x    = (const float*)d_in[0];
    const float* ea   = (const float*)d_in[1];
    const int*   ei   = (const int*)d_in[2];
    const float* e1w1 = (const float*)d_in[3];
    const float* e1b1 = (const float*)d_in[4];
    const float* e1w2 = (const float*)d_in[5];
    const float* e1b2 = (const float*)d_in[6];
    const float* n1w1 = (const float*)d_in[7];
    const float* n1b1 = (const float*)d_in[8];
    const float* n1w2 = (const float*)d_in[9];
    const float* n1b2 = (const float*)d_in[10];
    const float* n2w1 = (const float*)d_in[11];
    const float* n2b1 = (const float*)d_in[12];
    const float* n2w2 = (const float*)d_in[13];
    const float* n2b2 = (const float*)d_in[14];
    const float* e2w1 = (const float*)d_in[15];
    const float* e2b1 = (const float*)d_in[16];
    const float* e2w2 = (const float*)d_in[17];
    const float* e2b2 = (const float*)d_in[18];

    const int* row = ei;
    const int* col = ei + NE;

    float* out = (float*)d_out;
    float* x2  = out;
    float* e2o = out + (size_t)NN * 128;

    bf16 *wh, *wl, *xh, *xl, *e1h, *e1l, *x1h, *x1l, *x2h, *x2l;
    float* x1p;
    cudaGetSymbolAddress((void**)&wh, g_wh);
    cudaGetSymbolAddress((void**)&wl, g_wl);
    cudaGetSymbolAddress((void**)&xh, g_xh);
    cudaGetSymbolAddress((void**)&xl, g_xl);
    cudaGetSymbolAddress((void**)&e1h, g_e1h);
    cudaGetSymbolAddress((void**)&e1l, g_e1l);
    cudaGetSymbolAddress((void**)&x1h, g_x1h);
    cudaGetSymbolAddress((void**)&x1l, g_x1l);
    cudaGetSymbolAddress((void**)&x2h, g_x2h);
    cudaGetSymbolAddress((void**)&x2l, g_x2l);
    cudaGetSymbolAddress((void**)&x1p, g_x1);

    wprep_all<<<(229376 + 255) / 256, 256>>>(e1w1, e1w2, n1w1, n1w2,
                                             n2w1, n2w2, e2w1, e2w2, wh, wl);
    zero_kernel<<<1024, NTH>>>(x2);
    prep_split<<<512, 256>>>(x,  xh, xl, (size_t)NN * 32);
    prep_split<<<2048, 256>>>(ea, e1h, e1l, (size_t)NE * 32);

    int smemBytes = (int)sizeof(SM);
    cudaFuncSetAttribute(phaseA, cudaFuncAttributeMaxDynamicSharedMemorySize, smemBytes);
    cudaFuncSetAttribute(phaseB, cudaFuncAttributeMaxDynamicSharedMemorySize, smemBytes);
    cudaFuncSetAttribute(phaseC, cudaFuncAttributeMaxDynamicSharedMemorySize, smemBytes);

    phaseA<<<NE / TILE, NTH, smemBytes>>>(row, col, e1b1, e1b2, n1b1, n1b2);
    prep_split<<<512, 256>>>(x1p, x1h, x1l, (size_t)NN * 32);
    phaseB<<<NE / TILE, NTH, smemBytes>>>(row, col, n2b1, n2b2, x2);
    prep_split<<<512, 256>>>(x2, x2h, x2l, (size_t)NN * 32);
    phaseC<<<NE / TILE, NTH, smemBytes>>>(row, col, e2b1, e2b2, e2o);
}

// round 5
// speedup vs baseline: 4.2199x; 1.1132x over previous
#include <cuda_runtime.h>
#include <cuda_bf16.h>
#include <cstdint>

#define NN 40000
#define NE 640000
#define TILE 96
#define NTH 256
#define NBLK ((NE + TILE - 1) / TILE)   // 6667 (last block: 64 edges)
#define SA 392   // A-plane smem stride (halves)
#define SW 72    // W-plane smem stride (halves)

typedef __nv_bfloat16 bf16;
typedef unsigned int u32;

// ---- device scratch ----
__device__ bf16  g_e1h[(size_t)NE * 128];   // ea-split before phase A, e1-split after
__device__ bf16  g_e1l[(size_t)NE * 128];
__device__ float g_x1[(size_t)NN * 128];
__device__ bf16  g_xh[(size_t)NN * 128];
__device__ bf16  g_xl[(size_t)NN * 128];
__device__ bf16  g_x1h[(size_t)NN * 128];
__device__ bf16  g_x1l[(size_t)NN * 128];
__device__ bf16  g_x2h[(size_t)NN * 128];
__device__ bf16  g_x2l[(size_t)NN * 128];
__device__ bf16  g_wh[229376];
__device__ bf16  g_wl[229376];

#define W_E1W1 0
#define W_E1W2 49152
#define W_N1W1 65536
#define W_N1W2 98304
#define W_N2W1 114688
#define W_N2W2 147456
#define W_E2W1 163840
#define W_E2W2 212992

struct SM {
    bf16 Ah[TILE * SA];     // 75264 B
    bf16 Al[TILE * SA];     // 75264 B
    bf16 Wh[2][128 * SW];   // 36864 B
    bf16 Wl[2][128 * SW];   // 36864 B
    float b1[128];
    float b2[128];
    int rowI[TILE];
    int colI[TILE];
};                          // ~226 KB

// ---- helpers ----
__device__ __forceinline__ u32 cvta(const void* p) {
    return (u32)__cvta_generic_to_shared(p);
}
__device__ __forceinline__ void cpasync16(u32 dst, const void* src) {
    asm volatile("cp.async.cg.shared.global [%0], [%1], 16;" :: "r"(dst), "l"(src) : "memory");
}
__device__ __forceinline__ void cp_commit() {
    asm volatile("cp.async.commit_group;" ::: "memory");
}
__device__ __forceinline__ void cp_wait0() {
    asm volatile("cp.async.wait_group 0;" ::: "memory");
}
__device__ __forceinline__ void cp_wait1() {
    asm volatile("cp.async.wait_group 1;" ::: "memory");
}
__device__ __forceinline__ void ldsm4(u32 addr, u32& r0, u32& r1, u32& r2, u32& r3) {
    asm volatile("ldmatrix.sync.aligned.m8n8.x4.shared.b16 {%0,%1,%2,%3}, [%4];"
                 : "=r"(r0), "=r"(r1), "=r"(r2), "=r"(r3) : "r"(addr));
}
__device__ __forceinline__ void mma16816(float* c, const u32* a, const u32* b) {
    asm volatile("mma.sync.aligned.m16n8k16.row.col.f32.bf16.bf16.f32 "
                 "{%0,%1,%2,%3}, {%4,%5,%6,%7}, {%8,%9}, {%0,%1,%2,%3};"
                 : "+f"(c[0]), "+f"(c[1]), "+f"(c[2]), "+f"(c[3])
                 : "r"(a[0]), "r"(a[1]), "r"(a[2]), "r"(a[3]), "r"(b[0]), "r"(b[1]));
}
__device__ __forceinline__ void red2(float* p, float v0, float v1) {
    asm volatile("red.global.add.v2.f32 [%0], {%1,%2};" :: "l"(p), "f"(v0), "f"(v1) : "memory");
}
__device__ __forceinline__ void split2(float x, bf16& h, bf16& l) {
    h = __float2bfloat16_rn(x);
    l = __float2bfloat16_rn(x - __bfloat162float(h));
}
__device__ __forceinline__ void store_h2(bf16* ph, bf16* pl, float x0, float x1) {
    bf16 h0,l0,h1,l1; split2(x0,h0,l0); split2(x1,h1,l1);
    __nv_bfloat162 t;
    t.x=h0; t.y=h1; *(__nv_bfloat162*)ph = t;
    t.x=l0; t.y=l1; *(__nv_bfloat162*)pl = t;
}

__device__ __forceinline__ void stage_w(SM* sm, int buf,
    const bf16* __restrict__ gwh, const bf16* __restrict__ gwl, int K, int k0)
{
    u32 dh = cvta(&sm->Wh[buf][0]);
    u32 dl = cvta(&sm->Wl[buf][0]);
    for (int i = threadIdx.x; i < 1024; i += NTH) {
        int r = i >> 3, s = (i & 7) << 3;
        u32 off = (u32)((r * SW + s) * 2);
        const size_t g = (size_t)r * K + k0 + s;
        cpasync16(dh + off, gwh + g);
        cpasync16(dl + off, gwl + g);
    }
}

// GEMM: chunk0 of W must already be staged+committed by the caller.
// firstWait: pending cp.async groups allowed at chunk0 (1 = one trailing gather group).
__device__ __forceinline__ void run_gemm(SM* sm, int aCol, int K,
    const bf16* __restrict__ gwh, const bf16* __restrict__ gwl,
    float C[3][4][4], int firstWait)
{
    const int tid = threadIdx.x, lane = tid & 31, wid = tid >> 5;
    const int wM = wid >> 2, wN = wid & 3;
#pragma unroll
    for (int i = 0; i < 3; i++)
#pragma unroll
        for (int j = 0; j < 4; j++)
#pragma unroll
            for (int q = 0; q < 4; q++) C[i][j][q] = 0.f;

    const u32 ah_base = cvta(sm->Ah), al_base = cvta(sm->Al);
    const u32 wh_base[2] = { cvta(&sm->Wh[0][0]), cvta(&sm->Wh[1][0]) };
    const u32 wl_base[2] = { cvta(&sm->Wl[0][0]), cvta(&sm->Wl[1][0]) };

    const int aRow0 = wM * 48 + (lane & 15);
    const int aColL = (lane >> 4) * 8;
    const int bRowL = (lane & 7) + ((lane & 16) >> 1);
    const int bColL = (lane & 8);

    const int nchunk = K >> 6;
    for (int c = 0; c < nchunk; c++) {
        if (c == 0 && firstWait) cp_wait1(); else cp_wait0();
        __syncthreads();
        if (c + 1 < nchunk) {
            stage_w(sm, (c + 1) & 1, gwh, gwl, K, (c + 1) << 6);
            cp_commit();
        }
        const int buf = c & 1;
        const int k0 = c << 6;
#pragma unroll
        for (int kk = 0; kk < 64; kk += 16) {
            u32 a_h[3][4], a_l[3][4];
#pragma unroll
            for (int mi = 0; mi < 3; mi++) {
                u32 off = (u32)(((aRow0 + mi * 16) * SA + aCol + k0 + kk + aColL) * 2);
                ldsm4(ah_base + off, a_h[mi][0], a_h[mi][1], a_h[mi][2], a_h[mi][3]);
                ldsm4(al_base + off, a_l[mi][0], a_l[mi][1], a_l[mi][2], a_l[mi][3]);
            }
            u32 b_h[4][2], b_l[4][2];
#pragma unroll
            for (int pr = 0; pr < 2; pr++) {
                u32 off = (u32)(((wN * 32 + pr * 16 + bRowL) * SW + kk + bColL) * 2);
                ldsm4(wh_base[buf] + off, b_h[2*pr][0], b_h[2*pr][1], b_h[2*pr+1][0], b_h[2*pr+1][1]);
                ldsm4(wl_base[buf] + off, b_l[2*pr][0], b_l[2*pr][1], b_l[2*pr+1][0], b_l[2*pr+1][1]);
            }
#pragma unroll
            for (int mi = 0; mi < 3; mi++)
#pragma unroll
                for (int nb = 0; nb < 4; nb++) {
                    mma16816(C[mi][nb], a_h[mi], b_h[nb]);
                    mma16816(C[mi][nb], a_l[mi], b_h[nb]);
                    mma16816(C[mi][nb], a_h[mi], b_l[nb]);
                }
        }
    }
}

__device__ __forceinline__ void hidden_epilogue(SM* sm, float C[3][4][4]) {
    const int lane = threadIdx.x & 31, wid = threadIdx.x >> 5;
    const int wM = wid >> 2, wN = wid & 3, g = lane >> 2, q = (lane & 3) * 2;
#pragma unroll
    for (int mi = 0; mi < 3; mi++)
#pragma unroll
        for (int nb = 0; nb < 4; nb++) {
            int r = wM * 48 + mi * 16 + g, c = wN * 32 + nb * 8 + q;
            float b0 = sm->b1[c], b1v = sm->b1[c + 1];
            store_h2(&sm->Ah[r * SA + 256 + c], &sm->Al[r * SA + 256 + c],
                     fmaxf(C[mi][nb][0] + b0, 0.f), fmaxf(C[mi][nb][1] + b1v, 0.f));
            store_h2(&sm->Ah[(r + 8) * SA + 256 + c], &sm->Al[(r + 8) * SA + 256 + c],
                     fmaxf(C[mi][nb][2] + b0, 0.f), fmaxf(C[mi][nb][3] + b1v, 0.f));
        }
}

__device__ __forceinline__ void scatter_epilogue(SM* sm, float C[3][4][4],
                                                 float* __restrict__ dst, int rem) {
    const int lane = threadIdx.x & 31, wid = threadIdx.x >> 5;
    const int wM = wid >> 2, wN = wid & 3, g = lane >> 2, q = (lane & 3) * 2;
#pragma unroll
    for (int mi = 0; mi < 3; mi++)
#pragma unroll
        for (int nb = 0; nb < 4; nb++) {
            int r = wM * 48 + mi * 16 + g, c = wN * 32 + nb * 8 + q;
            float b0 = sm->b2[c], b1v = sm->b2[c + 1];
            if (r < rem)
                red2(dst + (size_t)sm->colI[r] * 128 + c,     C[mi][nb][0] + b0, C[mi][nb][1] + b1v);
            if (r + 8 < rem)
                red2(dst + (size_t)sm->colI[r + 8] * 128 + c, C[mi][nb][2] + b0, C[mi][nb][3] + b1v);
        }
}

// ---- prep kernels ----
__global__ void wprep_all(const float* __restrict__ w0, const float* __restrict__ w1,
                          const float* __restrict__ w2, const float* __restrict__ w3,
                          const float* __restrict__ w4, const float* __restrict__ w5,
                          const float* __restrict__ w6, const float* __restrict__ w7,
                          bf16* __restrict__ dh, bf16* __restrict__ dl)
{
    const int offs[9] = {0, 49152, 65536, 98304, 114688, 147456, 163840, 212992, 229376};
    const int Ks[8]   = {384, 128, 256, 128, 256, 128, 384, 128};
    const float* ws[8] = {w0, w1, w2, w3, w4, w5, w6, w7};
    int idx = blockIdx.x * blockDim.x + threadIdx.x;
    if (idx >= 229376) return;
    int m = 0;
    while (idx >= offs[m + 1]) m++;
    int local = idx - offs[m];
    int K = Ks[m];
    int n = local / K;
    int k = local - n * K;
    float v = ws[m][(size_t)k * 128 + n];
    bf16 h = __float2bfloat16_rn(v);
    dh[idx] = h;
    dl[idx] = __float2bfloat16_rn(v - __bfloat162float(h));
}

__global__ void prep_split(const float* __restrict__ src, bf16* __restrict__ dh,
                           bf16* __restrict__ dl, size_t n4)
{
    for (size_t i = (size_t)blockIdx.x * blockDim.x + threadIdx.x; i < n4;
         i += (size_t)gridDim.x * blockDim.x) {
        float4 v = ((const float4*)src)[i];
        bf16 h0,l0,h1,l1,h2,l2,h3,l3;
        split2(v.x,h0,l0); split2(v.y,h1,l1); split2(v.z,h2,l2); split2(v.w,h3,l3);
        __nv_bfloat162 a,b;
        a.x=h0; a.y=h1; b.x=h2; b.y=h3;
        ((__nv_bfloat162*)dh)[i*2] = a; ((__nv_bfloat162*)dh)[i*2+1] = b;
        a.x=l0; a.y=l1; b.x=l2; b.y=l3;
        ((__nv_bfloat162*)dl)[i*2] = a; ((__nv_bfloat162*)dl)[i*2+1] = b;
    }
}

__global__ void zero_kernel(float* __restrict__ x2out) {
    size_t n = (size_t)NN * 128;
    for (size_t i = (size_t)blockIdx.x * blockDim.x + threadIdx.x; i < n;
         i += (size_t)gridDim.x * blockDim.x) {
        g_x1[i] = 0.f;
        x2out[i] = 0.f;
    }
}

// gather one 128-col bf16 hi/lo row set via cp.async into A cols [seg, seg+128)
__device__ __forceinline__ void gather_idx(SM* sm, int seg,
    const bf16* __restrict__ srch, const bf16* __restrict__ srcl, const int* idx)
{
    u32 ah = cvta(sm->Ah), al = cvta(sm->Al);
    for (int i = threadIdx.x; i < TILE * 16; i += NTH) {
        int e = i >> 4, s = (i & 15) * 8;
        size_t r = (size_t)idx[e];
        u32 off = (u32)((e * SA + seg + s) * 2);
        cpasync16(ah + off, srch + r * 128 + s);
        cpasync16(al + off, srcl + r * 128 + s);
    }
}
__device__ __forceinline__ void gather_edge(SM* sm, int seg,
    const bf16* __restrict__ srch, const bf16* __restrict__ srcl, int e0)
{
    u32 ah = cvta(sm->Ah), al = cvta(sm->Al);
    for (int i = threadIdx.x; i < TILE * 16; i += NTH) {
        int e = i >> 4, s = (i & 15) * 8;
        size_t r = (size_t)min(e0 + e, NE - 1);
        u32 off = (u32)((e * SA + seg + s) * 2);
        cpasync16(ah + off, srch + r * 128 + s);
        cpasync16(al + off, srcl + r * 128 + s);
    }
}

__device__ __forceinline__ void load_idx(SM* sm, const int* row, const int* col, int e0)
{
    const int tid = threadIdx.x;
    if (tid < TILE)
        sm->rowI[tid] = (e0 + tid < NE) ? row[e0 + tid] : 0;
    else if (tid < 2 * TILE)
        sm->colI[tid - TILE] = (e0 + tid - TILE < NE) ? col[e0 + tid - TILE] : 0;
}

// ---- Phase A ----
__global__ void __launch_bounds__(NTH, 1)
phaseA(const int* __restrict__ row, const int* __restrict__ col,
       const float* __restrict__ e1b1, const float* __restrict__ e1b2,
       const float* __restrict__ n1b1, const float* __restrict__ n1b2)
{
    extern __shared__ char raw[];
    SM* sm = (SM*)raw;
    const int tid = threadIdx.x;
    const int e0 = blockIdx.x * TILE;
    const int rem = min(TILE, NE - e0);

    load_idx(sm, row, col, e0);
    __syncthreads();

    stage_w(sm, 0, g_wh + W_E1W1, g_wl + W_E1W1, 384, 0);
    gather_idx(sm, 0, g_xh, g_xl, sm->rowI);
    cp_commit();                                  // G1: W0 + seg0
    gather_idx(sm, 128, g_xh, g_xl, sm->colI);
    gather_edge(sm, 256, g_e1h, g_e1l, e0);       // ea-split pre-phase-A
    cp_commit();                                  // G2: rest
    if (tid < 128) sm->b1[tid] = e1b1[tid];

    float C[3][4][4];
    run_gemm(sm, 0, 384, g_wh + W_E1W1, g_wl + W_E1W1, C, 1);
    __syncthreads();
    hidden_epilogue(sm, C);
    stage_w(sm, 0, g_wh + W_E1W2, g_wl + W_E1W2, 128, 0);
    cp_commit();
    if (tid < 128) sm->b2[tid] = e1b2[tid];
    run_gemm(sm, 256, 128, g_wh + W_E1W2, g_wl + W_E1W2, C, 0);
    {   // e1 -> smem cols [128,256)
        const int lane = tid & 31, wid = tid >> 5;
        const int wM = wid >> 2, wN = wid & 3, g = lane >> 2, q = (lane & 3) * 2;
#pragma unroll
        for (int mi = 0; mi < 3; mi++)
#pragma unroll
            for (int nb = 0; nb < 4; nb++) {
                int r = wM * 48 + mi * 16 + g, c = wN * 32 + nb * 8 + q;
                float b0 = sm->b2[c], b1v = sm->b2[c + 1];
                store_h2(&sm->Ah[r * SA + 128 + c], &sm->Al[r * SA + 128 + c],
                         C[mi][nb][0] + b0, C[mi][nb][1] + b1v);
                store_h2(&sm->Ah[(r + 8) * SA + 128 + c], &sm->Al[(r + 8) * SA + 128 + c],
                         C[mi][nb][2] + b0, C[mi][nb][3] + b1v);
            }
    }
    __syncthreads();
    for (int i = tid; i < TILE * 16; i += NTH) {
        int e = i >> 4, s = (i & 15) * 8;
        if (e < rem) {
            *(uint4*)&g_e1h[(size_t)(e0 + e) * 128 + s] = *(const uint4*)&sm->Ah[e * SA + 128 + s];
            *(uint4*)&g_e1l[(size_t)(e0 + e) * 128 + s] = *(const uint4*)&sm->Al[e * SA + 128 + s];
        }
    }
    // MLP2: input cols [0,256) = [x[row], e1]
    stage_w(sm, 0, g_wh + W_N1W1, g_wl + W_N1W1, 256, 0);
    cp_commit();
    if (tid < 128) sm->b1[tid] = n1b1[tid];
    run_gemm(sm, 0, 256, g_wh + W_N1W1, g_wl + W_N1W1, C, 0);
    __syncthreads();
    hidden_epilogue(sm, C);
    stage_w(sm, 0, g_wh + W_N1W2, g_wl + W_N1W2, 128, 0);
    cp_commit();
    if (tid < 128) sm->b2[tid] = n1b2[tid];
    run_gemm(sm, 256, 128, g_wh + W_N1W2, g_wl + W_N1W2, C, 0);
    scatter_epilogue(sm, C, g_x1, rem);
}

// ---- Phase B ----
__global__ void __launch_bounds__(NTH, 1)
phaseB(const int* __restrict__ row, const int* __restrict__ col,
       const float* __restrict__ n2b1, const float* __restrict__ n2b2,
       float* __restrict__ x2out)
{
    extern __shared__ char raw[];
    SM* sm = (SM*)raw;
    const int tid = threadIdx.x;
    const int e0 = blockIdx.x * TILE;
    const int rem = min(TILE, NE - e0);

    load_idx(sm, row, col, e0);
    __syncthreads();

    stage_w(sm, 0, g_wh + W_N2W1, g_wl + W_N2W1, 256, 0);
    gather_idx(sm, 0, g_x1h, g_x1l, sm->rowI);
    cp_commit();                                  // G1
    gather_edge(sm, 128, g_e1h, g_e1l, e0);
    cp_commit();                                  // G2
    if (tid < 128) sm->b1[tid] = n2b1[tid];

    float C[3][4][4];
    run_gemm(sm, 0, 256, g_wh + W_N2W1, g_wl + W_N2W1, C, 1);
    __syncthreads();
    hidden_epilogue(sm, C);
    stage_w(sm, 0, g_wh + W_N2W2, g_wl + W_N2W2, 128, 0);
    cp_commit();
    if (tid < 128) sm->b2[tid] = n2b2[tid];
    run_gemm(sm, 256, 128, g_wh + W_N2W2, g_wl + W_N2W2, C, 0);
    scatter_epilogue(sm, C, x2out, rem);
}

// ---- Phase C ----
__global__ void __launch_bounds__(NTH, 1)
phaseC(const int* __restrict__ row, const int* __restrict__ col,
       const float* __restrict__ e2b1, const float* __restrict__ e2b2,
       float* __restrict__ e2out)
{
    extern __shared__ char raw[];
    SM* sm = (SM*)raw;
    const int tid = threadIdx.x;
    const int e0 = blockIdx.x * TILE;
    const int rem = min(TILE, NE - e0);

    load_idx(sm, row, col, e0);
    __syncthreads();

    stage_w(sm, 0, g_wh + W_E2W1, g_wl + W_E2W1, 384, 0);
    gather_idx(sm, 0, g_x2h, g_x2l, sm->rowI);
    cp_commit();                                  // G1
    gather_idx(sm, 128, g_x2h, g_x2l, sm->colI);
    gather_edge(sm, 256, g_e1h, g_e1l, e0);
    cp_commit();                                  // G2
    if (tid < 128) sm->b1[tid] = e2b1[tid];

    float C[3][4][4];
    run_gemm(sm, 0, 384, g_wh + W_E2W1, g_wl + W_E2W1, C, 1);
    __syncthreads();
    hidden_epilogue(sm, C);
    stage_w(sm, 0, g_wh + W_E2W2, g_wl + W_E2W2, 128, 0);
    cp_commit();
    if (tid < 128) sm->b2[tid] = e2b2[tid];
    run_gemm(sm, 256, 128, g_wh + W_E2W2, g_wl + W_E2W2, C, 0);
    __syncthreads();   // all reads done before reusing smem as fp32 staging

    float* sE = (float*)sm->Ah;   // 96*128*4 = 48 KB fits in Ah region
    {
        const int lane = tid & 31, wid = tid >> 5;
        const int wM = wid >> 2, wN = wid & 3, g = lane >> 2, q = (lane & 3) * 2;
#pragma unroll
        for (int mi = 0; mi < 3; mi++)
#pragma unroll
            for (int nb = 0; nb < 4; nb++) {
                int r = wM * 48 + mi * 16 + g, c = wN * 32 + nb * 8 + q;
                float b0 = sm->b2[c], b1v = sm->b2[c + 1];
                sE[r * 128 + c]           = C[mi][nb][0] + b0;
                sE[r * 128 + c + 1]       = C[mi][nb][1] + b1v;
                sE[(r + 8) * 128 + c]     = C[mi][nb][2] + b0;
                sE[(r + 8) * 128 + c + 1] = C[mi][nb][3] + b1v;
            }
    }
    __syncthreads();
    for (int i = tid; i < TILE * 32; i += NTH) {
        int e = i >> 5, s = (i & 31) * 4;
        if (e < rem)
            *(float4*)&e2out[(size_t)(e0 + e) * 128 + s] = *(const float4*)&sE[e * 128 + s];
    }
}

extern "C" void kernel_launch(void* const* d_in, const int* in_sizes, int n_in,
                              void* d_out, int out_size)
{
    const float* x    = (const float*)d_in[0];
    const float* ea   = (const float*)d_in[1];
    const int*   ei   = (const int*)d_in[2];
    const float* e1w1 = (const float*)d_in[3];
    const float* e1b1 = (const float*)d_in[4];
    const float* e1w2 = (const float*)d_in[5];
    const float* e1b2 = (const float*)d_in[6];
    const float* n1w1 = (const float*)d_in[7];
    const float* n1b1 = (const float*)d_in[8];
    const float* n1w2 = (const float*)d_in[9];
    const float* n1b2 = (const float*)d_in[10];
    const float* n2w1 = (const float*)d_in[11];
    const float* n2b1 = (const float*)d_in[12];
    const float* n2w2 = (const float*)d_in[13];
    const float* n2b2 = (const float*)d_in[14];
    const float* e2w1 = (const float*)d_in[15];
    const float* e2b1 = (const float*)d_in[16];
    const float* e2w2 = (const float*)d_in[17];
    const float* e2b2 = (const float*)d_in[18];

    const int* row = ei;
    const int* col = ei + NE;

    float* out = (float*)d_out;
    float* x2  = out;
    float* e2o = out + (size_t)NN * 128;

    bf16 *wh, *wl, *xh, *xl, *e1h, *e1l, *x1h, *x1l, *x2h, *x2l;
    float* x1p;
    cudaGetSymbolAddress((void**)&wh, g_wh);
    cudaGetSymbolAddress((void**)&wl, g_wl);
    cudaGetSymbolAddress((void**)&xh, g_xh);
    cudaGetSymbolAddress((void**)&xl, g_xl);
    cudaGetSymbolAddress((void**)&e1h, g_e1h);
    cudaGetSymbolAddress((void**)&e1l, g_e1l);
    cudaGetSymbolAddress((void**)&x1h, g_x1h);
    cudaGetSymbolAddress((void**)&x1l, g_x1l);
    cudaGetSymbolAddress((void**)&x2h, g_x2h);
    cudaGetSymbolAddress((void**)&x2l, g_x2l);
    cudaGetSymbolAddress((void**)&x1p, g_x1);

    wprep_all<<<(229376 + 255) / 256, 256>>>(e1w1, e1w2, n1w1, n1w2,
                                             n2w1, n2w2, e2w1, e2w2, wh, wl);
    zero_kernel<<<1024, NTH>>>(x2);
    prep_split<<<512, 256>>>(x,  xh, xl, (size_t)NN * 32);
    prep_split<<<2048, 256>>>(ea, e1h, e1l, (size_t)NE * 32);

    int smemBytes = (int)sizeof(SM);
    cudaFuncSetAttribute(phaseA, cudaFuncAttributeMaxDynamicSharedMemorySize, smemBytes);
    cudaFuncSetAttribute(phaseB, cudaFuncAttributeMaxDynamicSharedMemorySize, smemBytes);
    cudaFuncSetAttribute(phaseC, cudaFuncAttributeMaxDynamicSharedMemorySize, smemBytes);

    phaseA<<<NBLK, NTH, smemBytes>>>(row, col, e1b1, e1b2, n1b1, n1b2);
    prep_split<<<512, 256>>>(x1p, x1h, x1l, (size_t)NN * 32);
    phaseB<<<NBLK, NTH, smemBytes>>>(row, col, n2b1, n2b2, x2);
    prep_split<<<512, 256>>>(x2, x2h, x2l, (size_t)NN * 32);
    phaseC<<<NBLK, NTH, smemBytes>>>(row, col, e2b1, e2b2, e2o);
}

// round 6
// speedup vs baseline: 4.2791x; 1.0140x over previous
#include <cuda_runtime.h>
#include <cuda_bf16.h>
#include <cstdint>

#define NN 40000
#define NE 640000
#define TILE 96
#define NTH 256
#define NBLK ((NE + TILE - 1) / TILE)   // 6667 (last block: 64 edges)
#define SA 392   // A-plane smem stride (halves)
#define SW 72    // W-plane smem stride (halves)

typedef __nv_bfloat16 bf16;
typedef unsigned int u32;

// ---- device scratch ----
__device__ bf16  g_e1h[(size_t)NE * 128];   // ea-split before phase A, e1-split after
__device__ bf16  g_e1l[(size_t)NE * 128];
__device__ float g_x1[(size_t)NN * 128];
__device__ bf16  g_xh[(size_t)NN * 128];
__device__ bf16  g_xl[(size_t)NN * 128];
__device__ bf16  g_x1h[(size_t)NN * 128];
__device__ bf16  g_x1l[(size_t)NN * 128];
__device__ bf16  g_x2h[(size_t)NN * 128];
__device__ bf16  g_x2l[(size_t)NN * 128];
__device__ bf16  g_wh[229376];
__device__ bf16  g_wl[229376];

#define W_E1W1 0
#define W_E1W2 49152
#define W_N1W1 65536
#define W_N1W2 98304
#define W_N2W1 114688
#define W_N2W2 147456
#define W_E2W1 163840
#define W_E2W2 212992

struct SM {
    bf16 Ah[TILE * SA];     // 75264 B
    bf16 Al[TILE * SA];     // 75264 B
    bf16 Wh[2][128 * SW];   // 36864 B (per-warp 16-row slices inside)
    bf16 Wl[2][128 * SW];   // 36864 B
    float b1[128];
    float b2[128];
    int rowI[TILE];
    int colI[TILE];
};                          // ~226 KB

// ---- helpers ----
__device__ __forceinline__ u32 cvta(const void* p) {
    return (u32)__cvta_generic_to_shared(p);
}
__device__ __forceinline__ void cpasync16(u32 dst, const void* src) {
    asm volatile("cp.async.cg.shared.global [%0], [%1], 16;" :: "r"(dst), "l"(src) : "memory");
}
__device__ __forceinline__ void cp_commit() {
    asm volatile("cp.async.commit_group;" ::: "memory");
}
__device__ __forceinline__ void cp_wait0() {
    asm volatile("cp.async.wait_group 0;" ::: "memory");
}
__device__ __forceinline__ void ldsm4(u32 addr, u32& r0, u32& r1, u32& r2, u32& r3) {
    asm volatile("ldmatrix.sync.aligned.m8n8.x4.shared.b16 {%0,%1,%2,%3}, [%4];"
                 : "=r"(r0), "=r"(r1), "=r"(r2), "=r"(r3) : "r"(addr));
}
__device__ __forceinline__ void mma16816(float* c, const u32* a, const u32* b) {
    asm volatile("mma.sync.aligned.m16n8k16.row.col.f32.bf16.bf16.f32 "
                 "{%0,%1,%2,%3}, {%4,%5,%6,%7}, {%8,%9}, {%0,%1,%2,%3};"
                 : "+f"(c[0]), "+f"(c[1]), "+f"(c[2]), "+f"(c[3])
                 : "r"(a[0]), "r"(a[1]), "r"(a[2]), "r"(a[3]), "r"(b[0]), "r"(b[1]));
}
__device__ __forceinline__ void red2(float* p, float v0, float v1) {
    asm volatile("red.global.add.v2.f32 [%0], {%1,%2};" :: "l"(p), "f"(v0), "f"(v1) : "memory");
}
__device__ __forceinline__ void split2(float x, bf16& h, bf16& l) {
    h = __float2bfloat16_rn(x);
    l = __float2bfloat16_rn(x - __bfloat162float(h));
}
__device__ __forceinline__ void store_h2(bf16* ph, bf16* pl, float x0, float x1) {
    bf16 h0,l0,h1,l1; split2(x0,h0,l0); split2(x1,h1,l1);
    __nv_bfloat162 t;
    t.x=h0; t.y=h1; *(__nv_bfloat162*)ph = t;
    t.x=l0; t.y=l1; *(__nv_bfloat162*)pl = t;
}

// warp-private staging: warp w stages its own 16 n-rows of the 64-k chunk
__device__ __forceinline__ void stage_w_warp(SM* sm, int buf,
    const bf16* __restrict__ gwh, const bf16* __restrict__ gwl, int K, int k0)
{
    const int lane = threadIdx.x & 31, w = threadIdx.x >> 5;
    u32 dh = cvta(&sm->Wh[buf][0]);
    u32 dl = cvta(&sm->Wl[buf][0]);
    // 16 rows x 64 halves = 128B/row = 8 cp16/row -> 128 cp16 per plane, 4 per lane
    for (int i = lane; i < 128; i += 32) {
        int r = w * 16 + (i >> 3), s = (i & 7) << 3;
        u32 off = (u32)((r * SW + s) * 2);
        size_t g = (size_t)r * K + k0 + s;
        cpasync16(dh + off, gwh + g);
        cpasync16(dl + off, gwl + g);
    }
}

// GEMM: C[96 x 16-per-warp] += A(smem, cols [aCol,aCol+K)) x W^T (warp-private staged)
// Mainloop has NO block barriers; firstBar=1 inserts one after the first wait
// (needed when A was filled by cp.async from other threads).
__device__ __forceinline__ void run_gemm(SM* sm, int aCol, int K,
    const bf16* __restrict__ gwh, const bf16* __restrict__ gwl,
    float C[6][2][4], int firstBar)
{
    const int tid = threadIdx.x, lane = tid & 31, w = tid >> 5;
#pragma unroll
    for (int i = 0; i < 6; i++)
#pragma unroll
        for (int j = 0; j < 2; j++)
#pragma unroll
            for (int q = 0; q < 4; q++) C[i][j][q] = 0.f;

    const u32 ah_base = cvta(sm->Ah), al_base = cvta(sm->Al);
    const u32 wh_base[2] = { cvta(&sm->Wh[0][0]), cvta(&sm->Wh[1][0]) };
    const u32 wl_base[2] = { cvta(&sm->Wl[0][0]), cvta(&sm->Wl[1][0]) };

    const int aRowL = lane & 15;
    const int aColL = (lane >> 4) * 8;
    const int bRow  = w * 16 + ((lane & 16) >> 1) + (lane & 7);
    const int bColL = lane & 8;

    stage_w_warp(sm, 0, gwh, gwl, K, 0);
    cp_commit();

    const int nchunk = K >> 6;
    for (int c = 0; c < nchunk; c++) {
        cp_wait0();                      // per-warp: own W chunk (+ any prior gathers)
        if (c == 0 && firstBar) __syncthreads();
        if (c + 1 < nchunk) {
            stage_w_warp(sm, (c + 1) & 1, gwh, gwl, K, (c + 1) << 6);
            cp_commit();
        }
        const int buf = c & 1, k0 = c << 6;
#pragma unroll
        for (int kk = 0; kk < 64; kk += 16) {
            u32 b_h[4], b_l[4];
            u32 offb = (u32)((bRow * SW + kk + bColL) * 2);
            ldsm4(wh_base[buf] + offb, b_h[0], b_h[1], b_h[2], b_h[3]);
            ldsm4(wl_base[buf] + offb, b_l[0], b_l[1], b_l[2], b_l[3]);
#pragma unroll
            for (int mi = 0; mi < 6; mi++) {
                u32 a_h[4], a_l[4];
                u32 offa = (u32)(((mi * 16 + aRowL) * SA + aCol + k0 + kk + aColL) * 2);
                ldsm4(ah_base + offa, a_h[0], a_h[1], a_h[2], a_h[3]);
                ldsm4(al_base + offa, a_l[0], a_l[1], a_l[2], a_l[3]);
                mma16816(C[mi][0], a_h, b_h);
                mma16816(C[mi][0], a_l, b_h);
                mma16816(C[mi][0], a_h, b_l);
                mma16816(C[mi][1], a_h, b_h + 2);
                mma16816(C[mi][1], a_l, b_h + 2);
                mma16816(C[mi][1], a_h, b_l + 2);
            }
        }
    }
}

// fragment owner: rows r=mi*16+(lane>>2), r+8 ; cols c=w*16+nb*8+(lane&3)*2
__device__ __forceinline__ void hidden_epilogue(SM* sm, float C[6][2][4]) {
    const int lane = threadIdx.x & 31, w = threadIdx.x >> 5;
    const int g = lane >> 2, q = (lane & 3) * 2;
#pragma unroll
    for (int mi = 0; mi < 6; mi++)
#pragma unroll
        for (int nb = 0; nb < 2; nb++) {
            int r = mi * 16 + g, c = w * 16 + nb * 8 + q;
            float b0 = sm->b1[c], b1v = sm->b1[c + 1];
            store_h2(&sm->Ah[r * SA + 256 + c], &sm->Al[r * SA + 256 + c],
                     fmaxf(C[mi][nb][0] + b0, 0.f), fmaxf(C[mi][nb][1] + b1v, 0.f));
            store_h2(&sm->Ah[(r + 8) * SA + 256 + c], &sm->Al[(r + 8) * SA + 256 + c],
                     fmaxf(C[mi][nb][2] + b0, 0.f), fmaxf(C[mi][nb][3] + b1v, 0.f));
        }
}

__device__ __forceinline__ void scatter_epilogue(SM* sm, float C[6][2][4],
                                                 float* __restrict__ dst, int rem) {
    const int lane = threadIdx.x & 31, w = threadIdx.x >> 5;
    const int g = lane >> 2, q = (lane & 3) * 2;
#pragma unroll
    for (int mi = 0; mi < 6; mi++)
#pragma unroll
        for (int nb = 0; nb < 2; nb++) {
            int r = mi * 16 + g, c = w * 16 + nb * 8 + q;
            float b0 = sm->b2[c], b1v = sm->b2[c + 1];
            if (r < rem)
                red2(dst + (size_t)sm->colI[r] * 128 + c,     C[mi][nb][0] + b0, C[mi][nb][1] + b1v);
            if (r + 8 < rem)
                red2(dst + (size_t)sm->colI[r + 8] * 128 + c, C[mi][nb][2] + b0, C[mi][nb][3] + b1v);
        }
}

// ---- prep kernels ----
__global__ void wprep_all(const float* __restrict__ w0, const float* __restrict__ w1,
                          const float* __restrict__ w2, const float* __restrict__ w3,
                          const float* __restrict__ w4, const float* __restrict__ w5,
                          const float* __restrict__ w6, const float* __restrict__ w7,
                          bf16* __restrict__ dh, bf16* __restrict__ dl)
{
    const int offs[9] = {0, 49152, 65536, 98304, 114688, 147456, 163840, 212992, 229376};
    const int Ks[8]   = {384, 128, 256, 128, 256, 128, 384, 128};
    const float* ws[8] = {w0, w1, w2, w3, w4, w5, w6, w7};
    int idx = blockIdx.x * blockDim.x + threadIdx.x;
    if (idx >= 229376) return;
    int m = 0;
    while (idx >= offs[m + 1]) m++;
    int local = idx - offs[m];
    int K = Ks[m];
    int n = local / K;
    int k = local - n * K;
    float v = ws[m][(size_t)k * 128 + n];
    bf16 h = __float2bfloat16_rn(v);
    dh[idx] = h;
    dl[idx] = __float2bfloat16_rn(v - __bfloat162float(h));
}

__global__ void prep_split(const float* __restrict__ src, bf16* __restrict__ dh,
                           bf16* __restrict__ dl, size_t n4)
{
    for (size_t i = (size_t)blockIdx.x * blockDim.x + threadIdx.x; i < n4;
         i += (size_t)gridDim.x * blockDim.x) {
        float4 v = ((const float4*)src)[i];
        bf16 h0,l0,h1,l1,h2,l2,h3,l3;
        split2(v.x,h0,l0); split2(v.y,h1,l1); split2(v.z,h2,l2); split2(v.w,h3,l3);
        __nv_bfloat162 a,b;
        a.x=h0; a.y=h1; b.x=h2; b.y=h3;
        ((__nv_bfloat162*)dh)[i*2] = a; ((__nv_bfloat162*)dh)[i*2+1] = b;
        a.x=l0; a.y=l1; b.x=l2; b.y=l3;
        ((__nv_bfloat162*)dl)[i*2] = a; ((__nv_bfloat162*)dl)[i*2+1] = b;
    }
}

__global__ void zero_kernel(float* __restrict__ x2out) {
    size_t n = (size_t)NN * 128;
    for (size_t i = (size_t)blockIdx.x * blockDim.x + threadIdx.x; i < n;
         i += (size_t)gridDim.x * blockDim.x) {
        g_x1[i] = 0.f;
        x2out[i] = 0.f;
    }
}

__device__ __forceinline__ void gather_idx(SM* sm, int seg,
    const bf16* __restrict__ srch, const bf16* __restrict__ srcl, const int* idx)
{
    u32 ah = cvta(sm->Ah), al = cvta(sm->Al);
    for (int i = threadIdx.x; i < TILE * 16; i += NTH) {
        int e = i >> 4, s = (i & 15) * 8;
        size_t r = (size_t)idx[e];
        u32 off = (u32)((e * SA + seg + s) * 2);
        cpasync16(ah + off, srch + r * 128 + s);
        cpasync16(al + off, srcl + r * 128 + s);
    }
}
__device__ __forceinline__ void gather_edge(SM* sm, int seg,
    const bf16* __restrict__ srch, const bf16* __restrict__ srcl, int e0)
{
    u32 ah = cvta(sm->Ah), al = cvta(sm->Al);
    for (int i = threadIdx.x; i < TILE * 16; i += NTH) {
        int e = i >> 4, s = (i & 15) * 8;
        size_t r = (size_t)min(e0 + e, NE - 1);
        u32 off = (u32)((e * SA + seg + s) * 2);
        cpasync16(ah + off, srch + r * 128 + s);
        cpasync16(al + off, srcl + r * 128 + s);
    }
}

__device__ __forceinline__ void load_idx(SM* sm, const int* row, const int* col, int e0)
{
    const int tid = threadIdx.x;
    if (tid < TILE)
        sm->rowI[tid] = (e0 + tid < NE) ? row[e0 + tid] : 0;
    else if (tid < 2 * TILE)
        sm->colI[tid - TILE] = (e0 + tid - TILE < NE) ? col[e0 + tid - TILE] : 0;
}

// ---- Phase A ----
__global__ void __launch_bounds__(NTH, 1)
phaseA(const int* __restrict__ row, const int* __restrict__ col,
       const float* __restrict__ e1b1, const float* __restrict__ e1b2,
       const float* __restrict__ n1b1, const float* __restrict__ n1b2)
{
    extern __shared__ char raw[];
    SM* sm = (SM*)raw;
    const int tid = threadIdx.x;
    const int e0 = blockIdx.x * TILE;
    const int rem = min(TILE, NE - e0);

    load_idx(sm, row, col, e0);
    __syncthreads();

    gather_idx(sm, 0, g_xh, g_xl, sm->rowI);
    gather_idx(sm, 128, g_xh, g_xl, sm->colI);
    gather_edge(sm, 256, g_e1h, g_e1l, e0);       // ea-split pre-phase-A
    cp_commit();
    if (tid < 128) sm->b1[tid] = e1b1[tid];

    float C[6][2][4];
    // MLP1 layer1 (K=384)
    run_gemm(sm, 0, 384, g_wh + W_E1W1, g_wl + W_E1W1, C, 1);
    __syncthreads();                // all warps done reading A before hidden write
    hidden_epilogue(sm, C);
    if (tid < 128) sm->b2[tid] = e1b2[tid];
    __syncthreads();                // hidden + b2 visible
    run_gemm(sm, 256, 128, g_wh + W_E1W2, g_wl + W_E1W2, C, 0);
    {   // e1 frag -> smem cols [128,256)  (disjoint from GEMM2 reads [256,384))
        const int lane = tid & 31, w = tid >> 5;
        const int g = lane >> 2, q = (lane & 3) * 2;
#pragma unroll
        for (int mi = 0; mi < 6; mi++)
#pragma unroll
            for (int nb = 0; nb < 2; nb++) {
                int r = mi * 16 + g, c = w * 16 + nb * 8 + q;
                float b0 = sm->b2[c], b1v = sm->b2[c + 1];
                store_h2(&sm->Ah[r * SA + 128 + c], &sm->Al[r * SA + 128 + c],
                         C[mi][nb][0] + b0, C[mi][nb][1] + b1v);
                store_h2(&sm->Ah[(r + 8) * SA + 128 + c], &sm->Al[(r + 8) * SA + 128 + c],
                         C[mi][nb][2] + b0, C[mi][nb][3] + b1v);
            }
    }
    if (tid < 128) sm->b1[tid] = n1b1[tid];       // b1 free (all passed pre-GEMM2 bar)
    __syncthreads();                // e1 + b1 visible
    for (int i = tid; i < TILE * 16; i += NTH) {
        int e = i >> 4, s = (i & 15) * 8;
        if (e < rem) {
            *(uint4*)&g_e1h[(size_t)(e0 + e) * 128 + s] = *(const uint4*)&sm->Ah[e * SA + 128 + s];
            *(uint4*)&g_e1l[(size_t)(e0 + e) * 128 + s] = *(const uint4*)&sm->Al[e * SA + 128 + s];
        }
    }
    // MLP2 layer1 (K=256, reads [0,256))
    run_gemm(sm, 0, 256, g_wh + W_N1W1, g_wl + W_N1W1, C, 0);
    hidden_epilogue(sm, C);         // writes [256,384): disjoint from GEMM1 reads
    if (tid < 128) sm->b2[tid] = n1b2[tid];
    __syncthreads();
    run_gemm(sm, 256, 128, g_wh + W_N1W2, g_wl + W_N1W2, C, 0);
    scatter_epilogue(sm, C, g_x1, rem);
}

// ---- Phase B ----
__global__ void __launch_bounds__(NTH, 1)
phaseB(const int* __restrict__ row, const int* __restrict__ col,
       const float* __restrict__ n2b1, const float* __restrict__ n2b2,
       float* __restrict__ x2out)
{
    extern __shared__ char raw[];
    SM* sm = (SM*)raw;
    const int tid = threadIdx.x;
    const int e0 = blockIdx.x * TILE;
    const int rem = min(TILE, NE - e0);

    load_idx(sm, row, col, e0);
    __syncthreads();

    gather_idx(sm, 0, g_x1h, g_x1l, sm->rowI);
    gather_edge(sm, 128, g_e1h, g_e1l, e0);
    cp_commit();
    if (tid < 128) sm->b1[tid] = n2b1[tid];

    float C[6][2][4];
    run_gemm(sm, 0, 256, g_wh + W_N2W1, g_wl + W_N2W1, C, 1);
    hidden_epilogue(sm, C);         // [256,384) disjoint from GEMM1 reads [0,256)
    if (tid < 128) sm->b2[tid] = n2b2[tid];
    __syncthreads();
    run_gemm(sm, 256, 128, g_wh + W_N2W2, g_wl + W_N2W2, C, 0);
    scatter_epilogue(sm, C, x2out, rem);
}

// ---- Phase C ----
__global__ void __launch_bounds__(NTH, 1)
phaseC(const int* __restrict__ row, const int* __restrict__ col,
       const float* __restrict__ e2b1, const float* __restrict__ e2b2,
       float* __restrict__ e2out)
{
    extern __shared__ char raw[];
    SM* sm = (SM*)raw;
    const int tid = threadIdx.x;
    const int e0 = blockIdx.x * TILE;
    const int rem = min(TILE, NE - e0);

    load_idx(sm, row, col, e0);
    __syncthreads();

    gather_idx(sm, 0, g_x2h, g_x2l, sm->rowI);
    gather_idx(sm, 128, g_x2h, g_x2l, sm->colI);
    gather_edge(sm, 256, g_e1h, g_e1l, e0);
    cp_commit();
    if (tid < 128) sm->b1[tid] = e2b1[tid];

    float C[6][2][4];
    run_gemm(sm, 0, 384, g_wh + W_E2W1, g_wl + W_E2W1, C, 1);
    __syncthreads();                // all warps done reading A[0,384)
    hidden_epilogue(sm, C);
    if (tid < 128) sm->b2[tid] = e2b2[tid];
    __syncthreads();
    run_gemm(sm, 256, 128, g_wh + W_E2W2, g_wl + W_E2W2, C, 0);
    __syncthreads();                // all reads done before reusing Ah as fp32 staging

    float* sE = (float*)sm->Ah;     // 96*128*4 = 48 KB
    {
        const int lane = tid & 31, w = tid >> 5;
        const int g = lane >> 2, q = (lane & 3) * 2;
#pragma unroll
        for (int mi = 0; mi < 6; mi++)
#pragma unroll
            for (int nb = 0; nb < 2; nb++) {
                int r = mi * 16 + g, c = w * 16 + nb * 8 + q;
                float b0 = sm->b2[c], b1v = sm->b2[c + 1];
                sE[r * 128 + c]           = C[mi][nb][0] + b0;
                sE[r * 128 + c + 1]       = C[mi][nb][1] + b1v;
                sE[(r + 8) * 128 + c]     = C[mi][nb][2] + b0;
                sE[(r + 8) * 128 + c + 1] = C[mi][nb][3] + b1v;
            }
    }
    __syncthreads();
    for (int i = tid; i < TILE * 32; i += NTH) {
        int e = i >> 5, s = (i & 31) * 4;
        if (e < rem)
            *(float4*)&e2out[(size_t)(e0 + e) * 128 + s] = *(const float4*)&sE[e * 128 + s];
    }
}

extern "C" void kernel_launch(void* const* d_in, const int* in_sizes, int n_in,
                              void* d_out, int out_size)
{
    const float* x    = (const float*)d_in[0];
    const float* ea   = (const float*)d_in[1];
    const int*   ei   = (const int*)d_in[2];
    const float* e1w1 = (const float*)d_in[3];
    const float* e1b1 = (const float*)d_in[4];
    const float* e1w2 = (const float*)d_in[5];
    const float* e1b2 = (const float*)d_in[6];
    const float* n1w1 = (const float*)d_in[7];
    const float* n1b1 = (const float*)d_in[8];
    const float* n1w2 = (const float*)d_in[9];
    const float* n1b2 = (const float*)d_in[10];
    const float* n2w1 = (const float*)d_in[11];
    const float* n2b1 = (const float*)d_in[12];
    const float* n2w2 = (const float*)d_in[13];
    const float* n2b2 = (const float*)d_in[14];
    const float* e2w1 = (const float*)d_in[15];
    const float* e2b1 = (const float*)d_in[16];
    const float* e2w2 = (const float*)d_in[17];
    const float* e2b2 = (const float*)d_in[18];

    const int* row = ei;
    const int* col = ei + NE;

    float* out = (float*)d_out;
    float* x2  = out;
    float* e2o = out + (size_t)NN * 128;

    bf16 *wh, *wl, *xh, *xl, *e1h, *e1l, *x1h, *x1l, *x2h, *x2l;
    float* x1p;
    cudaGetSymbolAddress((void**)&wh, g_wh);
    cudaGetSymbolAddress((void**)&wl, g_wl);
    cudaGetSymbolAddress((void**)&xh, g_xh);
    cudaGetSymbolAddress((void**)&xl, g_xl);
    cudaGetSymbolAddress((void**)&e1h, g_e1h);
    cudaGetSymbolAddress((void**)&e1l, g_e1l);
    cudaGetSymbolAddress((void**)&x1h, g_x1h);
    cudaGetSymbolAddress((void**)&x1l, g_x1l);
    cudaGetSymbolAddress((void**)&x2h, g_x2h);
    cudaGetSymbolAddress((void**)&x2l, g_x2l);
    cudaGetSymbolAddress((void**)&x1p, g_x1);

    wprep_all<<<(229376 + 255) / 256, 256>>>(e1w1, e1w2, n1w1, n1w2,
                                             n2w1, n2w2, e2w1, e2w2, wh, wl);
    zero_kernel<<<1024, NTH>>>(x2);
    prep_split<<<512, 256>>>(x,  xh, xl, (size_t)NN * 32);
    prep_split<<<2048, 256>>>(ea, e1h, e1l, (size_t)NE * 32);

    int smemBytes = (int)sizeof(SM);
    cudaFuncSetAttribute(phaseA, cudaFuncAttributeMaxDynamicSharedMemorySize, smemBytes);
    cudaFuncSetAttribute(phaseB, cudaFuncAttributeMaxDynamicSharedMemorySize, smemBytes);
    cudaFuncSetAttribute(phaseC, cudaFuncAttributeMaxDynamicSharedMemorySize, smemBytes);

    phaseA<<<NBLK, NTH, smemBytes>>>(row, col, e1b1, e1b2, n1b1, n1b2);
    prep_split<<<512, 256>>>(x1p, x1h, x1l, (size_t)NN * 32);
    phaseB<<<NBLK, NTH, smemBytes>>>(row, col, n2b1, n2b2, x2);
    prep_split<<<512, 256>>>(x2, x2h, x2l, (size_t)NN * 32);
    phaseC<<<NBLK, NTH, smemBytes>>>(row, col, e2b1, e2b2, e2o);
}

// round 7
// speedup vs baseline: 5.6014x; 1.3090x over previous
#include <cuda_runtime.h>
#include <cuda_fp16.h>
#include <cstdint>

#define NN 40000
#define NE 640000
#define TILE 96
#define NTH 256
#define NBLK ((NE + TILE - 1) / TILE)   // 6667 (last block: 64 edges)
#define SA 392   // A-plane smem stride (halves)
#define SW 72    // W-plane smem stride (halves)

typedef unsigned int u32;

// ---- device scratch ----
__device__ __half g_e1h[(size_t)NE * 128];   // ea-split before phase A, e1-split after
__device__ __half g_e1l[(size_t)NE * 128];
__device__ float  g_x1[(size_t)NN * 128];
__device__ __half g_xh[(size_t)NN * 128];
__device__ __half g_xl[(size_t)NN * 128];
__device__ __half g_x1h[(size_t)NN * 128];
__device__ __half g_x1l[(size_t)NN * 128];
__device__ __half g_x2h[(size_t)NN * 128];
__device__ __half g_x2l[(size_t)NN * 128];
__device__ __half g_w[229376];               // single fp16 plane, transposed [n][k]

#define W_E1W1 0
#define W_E1W2 49152
#define W_N1W1 65536
#define W_N1W2 98304
#define W_N2W1 114688
#define W_N2W2 147456
#define W_E2W1 163840
#define W_E2W2 212992

struct SM {
    __half Ah[TILE * SA];     // 75264 B
    __half Al[TILE * SA];     // 75264 B
    __half W[2][128 * SW];    // 36864 B (double buffer, single plane)
    float b1[128];
    float b2[128];
    int rowI[TILE];
    int colI[TILE];
};                            // ~189 KB

// ---- helpers ----
__device__ __forceinline__ u32 cvta(const void* p) {
    return (u32)__cvta_generic_to_shared(p);
}
__device__ __forceinline__ void cpasync16(u32 dst, const void* src) {
    asm volatile("cp.async.cg.shared.global [%0], [%1], 16;" :: "r"(dst), "l"(src) : "memory");
}
__device__ __forceinline__ void cp_commit() {
    asm volatile("cp.async.commit_group;" ::: "memory");
}
__device__ __forceinline__ void cp_wait0() {
    asm volatile("cp.async.wait_group 0;" ::: "memory");
}
__device__ __forceinline__ void cp_wait1() {
    asm volatile("cp.async.wait_group 1;" ::: "memory");
}
__device__ __forceinline__ void ldsm4(u32 addr, u32& r0, u32& r1, u32& r2, u32& r3) {
    asm volatile("ldmatrix.sync.aligned.m8n8.x4.shared.b16 {%0,%1,%2,%3}, [%4];"
                 : "=r"(r0), "=r"(r1), "=r"(r2), "=r"(r3) : "r"(addr));
}
__device__ __forceinline__ void mma16816(float* c, const u32* a, const u32* b) {
    asm volatile("mma.sync.aligned.m16n8k16.row.col.f32.f16.f16.f32 "
                 "{%0,%1,%2,%3}, {%4,%5,%6,%7}, {%8,%9}, {%0,%1,%2,%3};"
                 : "+f"(c[0]), "+f"(c[1]), "+f"(c[2]), "+f"(c[3])
                 : "r"(a[0]), "r"(a[1]), "r"(a[2]), "r"(a[3]), "r"(b[0]), "r"(b[1]));
}
__device__ __forceinline__ void red2(float* p, float v0, float v1) {
    asm volatile("red.global.add.v2.f32 [%0], {%1,%2};" :: "l"(p), "f"(v0), "f"(v1) : "memory");
}
__device__ __forceinline__ void split2(float x, __half& h, __half& l) {
    h = __float2half_rn(x);
    l = __float2half_rn(x - __half2float(h));
}
__device__ __forceinline__ void store_h2(__half* ph, __half* pl, float x0, float x1) {
    __half h0,l0,h1,l1; split2(x0,h0,l0); split2(x1,h1,l1);
    __half2 t;
    t.x=h0; t.y=h1; *(__half2*)ph = t;
    t.x=l0; t.y=l1; *(__half2*)pl = t;
}

// block-wide staging of one 64-k chunk (single fp16 plane, 16 KB)
__device__ __forceinline__ void stage_w(SM* sm, int buf,
    const __half* __restrict__ gw, int K, int k0)
{
    u32 d = cvta(&sm->W[buf][0]);
    for (int i = threadIdx.x; i < 1024; i += NTH) {
        int r = i >> 3, s = (i & 7) << 3;
        cpasync16(d + (u32)((r * SW + s) * 2), gw + (size_t)r * K + k0 + s);
    }
}

// GEMM: C[96 x 128] += A(smem 2-plane fp16, cols [aCol,aCol+K)) x W^T(fp16 1-plane)
// Warp tile 48x32: wM = wid>>2 (0-1), wN = wid&3 (0-3).
__device__ __forceinline__ void run_gemm(SM* sm, int aCol, int K,
    const __half* __restrict__ gw, float C[3][4][4], int firstWait)
{
    const int tid = threadIdx.x, lane = tid & 31, wid = tid >> 5;
    const int wM = wid >> 2, wN = wid & 3;
#pragma unroll
    for (int i = 0; i < 3; i++)
#pragma unroll
        for (int j = 0; j < 4; j++)
#pragma unroll
            for (int q = 0; q < 4; q++) C[i][j][q] = 0.f;

    const u32 ah_base = cvta(sm->Ah), al_base = cvta(sm->Al);
    const u32 w_base[2] = { cvta(&sm->W[0][0]), cvta(&sm->W[1][0]) };

    const int aRow0 = wM * 48 + (lane & 15);
    const int aColL = (lane >> 4) * 8;
    const int bRowL = (lane & 7) + ((lane & 16) >> 1);
    const int bColL = lane & 8;

    const int nchunk = K >> 6;
    for (int c = 0; c < nchunk; c++) {
        if (c == 0 && firstWait) cp_wait1(); else cp_wait0();
        __syncthreads();
        if (c + 1 < nchunk) {
            stage_w(sm, (c + 1) & 1, gw, K, (c + 1) << 6);
            cp_commit();
        }
        const int buf = c & 1, k0 = c << 6;
#pragma unroll
        for (int kk = 0; kk < 64; kk += 16) {
            u32 a_h[3][4], a_l[3][4];
#pragma unroll
            for (int mi = 0; mi < 3; mi++) {
                u32 off = (u32)(((aRow0 + mi * 16) * SA + aCol + k0 + kk + aColL) * 2);
                ldsm4(ah_base + off, a_h[mi][0], a_h[mi][1], a_h[mi][2], a_h[mi][3]);
                ldsm4(al_base + off, a_l[mi][0], a_l[mi][1], a_l[mi][2], a_l[mi][3]);
            }
            u32 b[4][2];
#pragma unroll
            for (int pr = 0; pr < 2; pr++) {
                u32 off = (u32)(((wN * 32 + pr * 16 + bRowL) * SW + kk + bColL) * 2);
                ldsm4(w_base[buf] + off, b[2*pr][0], b[2*pr][1], b[2*pr+1][0], b[2*pr+1][1]);
            }
#pragma unroll
            for (int mi = 0; mi < 3; mi++)
#pragma unroll
                for (int nb = 0; nb < 4; nb++) {
                    mma16816(C[mi][nb], a_h[mi], b[nb]);
                    mma16816(C[mi][nb], a_l[mi], b[nb]);
                }
        }
    }
}

// fragment owner: rows r=wM*48+mi*16+(lane>>2), r+8 ; cols c=wN*32+nb*8+(lane&3)*2
__device__ __forceinline__ void hidden_epilogue(SM* sm, float C[3][4][4]) {
    const int lane = threadIdx.x & 31, wid = threadIdx.x >> 5;
    const int wM = wid >> 2, wN = wid & 3, g = lane >> 2, q = (lane & 3) * 2;
#pragma unroll
    for (int mi = 0; mi < 3; mi++)
#pragma unroll
        for (int nb = 0; nb < 4; nb++) {
            int r = wM * 48 + mi * 16 + g, c = wN * 32 + nb * 8 + q;
            float b0 = sm->b1[c], b1v = sm->b1[c + 1];
            store_h2(&sm->Ah[r * SA + 256 + c], &sm->Al[r * SA + 256 + c],
                     fmaxf(C[mi][nb][0] + b0, 0.f), fmaxf(C[mi][nb][1] + b1v, 0.f));
            store_h2(&sm->Ah[(r + 8) * SA + 256 + c], &sm->Al[(r + 8) * SA + 256 + c],
                     fmaxf(C[mi][nb][2] + b0, 0.f), fmaxf(C[mi][nb][3] + b1v, 0.f));
        }
}

__device__ __forceinline__ void scatter_epilogue(SM* sm, float C[3][4][4],
                                                 float* __restrict__ dst, int rem) {
    const int lane = threadIdx.x & 31, wid = threadIdx.x >> 5;
    const int wM = wid >> 2, wN = wid & 3, g = lane >> 2, q = (lane & 3) * 2;
#pragma unroll
    for (int mi = 0; mi < 3; mi++)
#pragma unroll
        for (int nb = 0; nb < 4; nb++) {
            int r = wM * 48 + mi * 16 + g, c = wN * 32 + nb * 8 + q;
            float b0 = sm->b2[c], b1v = sm->b2[c + 1];
            if (r < rem)
                red2(dst + (size_t)sm->colI[r] * 128 + c,     C[mi][nb][0] + b0, C[mi][nb][1] + b1v);
            if (r + 8 < rem)
                red2(dst + (size_t)sm->colI[r + 8] * 128 + c, C[mi][nb][2] + b0, C[mi][nb][3] + b1v);
        }
}

// ---- prep kernels ----
__global__ void wprep_all(const float* __restrict__ w0, const float* __restrict__ w1,
                          const float* __restrict__ w2, const float* __restrict__ w3,
                          const float* __restrict__ w4, const float* __restrict__ w5,
                          const float* __restrict__ w6, const float* __restrict__ w7,
                          __half* __restrict__ dw)
{
    const int offs[9] = {0, 49152, 65536, 98304, 114688, 147456, 163840, 212992, 229376};
    const int Ks[8]   = {384, 128, 256, 128, 256, 128, 384, 128};
    const float* ws[8] = {w0, w1, w2, w3, w4, w5, w6, w7};
    int idx = blockIdx.x * blockDim.x + threadIdx.x;
    if (idx >= 229376) return;
    int m = 0;
    while (idx >= offs[m + 1]) m++;
    int local = idx - offs[m];
    int K = Ks[m];
    int n = local / K;
    int k = local - n * K;
    dw[idx] = __float2half_rn(ws[m][(size_t)k * 128 + n]);
}

__global__ void prep_split(const float* __restrict__ src, __half* __restrict__ dh,
                           __half* __restrict__ dl, size_t n4)
{
    for (size_t i = (size_t)blockIdx.x * blockDim.x + threadIdx.x; i < n4;
         i += (size_t)gridDim.x * blockDim.x) {
        float4 v = ((const float4*)src)[i];
        __half h0,l0,h1,l1,h2,l2,h3,l3;
        split2(v.x,h0,l0); split2(v.y,h1,l1); split2(v.z,h2,l2); split2(v.w,h3,l3);
        __half2 a,b;
        a.x=h0; a.y=h1; b.x=h2; b.y=h3;
        ((__half2*)dh)[i*2] = a; ((__half2*)dh)[i*2+1] = b;
        a.x=l0; a.y=l1; b.x=l2; b.y=l3;
        ((__half2*)dl)[i*2] = a; ((__half2*)dl)[i*2+1] = b;
    }
}

__global__ void zero_kernel(float* __restrict__ x2out) {
    size_t n = (size_t)NN * 128;
    for (size_t i = (size_t)blockIdx.x * blockDim.x + threadIdx.x; i < n;
         i += (size_t)gridDim.x * blockDim.x) {
        g_x1[i] = 0.f;
        x2out[i] = 0.f;
    }
}

__device__ __forceinline__ void gather_idx(SM* sm, int seg,
    const __half* __restrict__ srch, const __half* __restrict__ srcl, const int* idx)
{
    u32 ah = cvta(sm->Ah), al = cvta(sm->Al);
    for (int i = threadIdx.x; i < TILE * 16; i += NTH) {
        int e = i >> 4, s = (i & 15) * 8;
        size_t r = (size_t)idx[e];
        u32 off = (u32)((e * SA + seg + s) * 2);
        cpasync16(ah + off, srch + r * 128 + s);
        cpasync16(al + off, srcl + r * 128 + s);
    }
}
__device__ __forceinline__ void gather_edge(SM* sm, int seg,
    const __half* __restrict__ srch, const __half* __restrict__ srcl, int e0)
{
    u32 ah = cvta(sm->Ah), al = cvta(sm->Al);
    for (int i = threadIdx.x; i < TILE * 16; i += NTH) {
        int e = i >> 4, s = (i & 15) * 8;
        size_t r = (size_t)min(e0 + e, NE - 1);
        u32 off = (u32)((e * SA + seg + s) * 2);
        cpasync16(ah + off, srch + r * 128 + s);
        cpasync16(al + off, srcl + r * 128 + s);
    }
}

__device__ __forceinline__ void load_idx(SM* sm, const int* row, const int* col, int e0)
{
    const int tid = threadIdx.x;
    if (tid < TILE)
        sm->rowI[tid] = (e0 + tid < NE) ? row[e0 + tid] : 0;
    else if (tid < 2 * TILE)
        sm->colI[tid - TILE] = (e0 + tid - TILE < NE) ? col[e0 + tid - TILE] : 0;
}

// ---- Phase A ----
__global__ void __launch_bounds__(NTH, 1)
phaseA(const int* __restrict__ row, const int* __restrict__ col,
       const float* __restrict__ e1b1, const float* __restrict__ e1b2,
       const float* __restrict__ n1b1, const float* __restrict__ n1b2)
{
    extern __shared__ char raw[];
    SM* sm = (SM*)raw;
    const int tid = threadIdx.x;
    const int e0 = blockIdx.x * TILE;
    const int rem = min(TILE, NE - e0);

    load_idx(sm, row, col, e0);
    __syncthreads();

    stage_w(sm, 0, g_w + W_E1W1, 384, 0);
    gather_idx(sm, 0, g_xh, g_xl, sm->rowI);
    cp_commit();                                  // G1: W0 + seg0
    gather_idx(sm, 128, g_xh, g_xl, sm->colI);
    gather_edge(sm, 256, g_e1h, g_e1l, e0);       // ea-split pre-phase-A
    cp_commit();                                  // G2: rest
    if (tid < 128) sm->b1[tid] = e1b1[tid];

    float C[3][4][4];
    run_gemm(sm, 0, 384, g_w + W_E1W1, C, 1);
    __syncthreads();
    hidden_epilogue(sm, C);
    stage_w(sm, 0, g_w + W_E1W2, 128, 0);
    cp_commit();
    if (tid < 128) sm->b2[tid] = e1b2[tid];
    run_gemm(sm, 256, 128, g_w + W_E1W2, C, 0);
    {   // e1 -> smem cols [128,256)  (disjoint from layer2 reads [256,384))
        const int lane = tid & 31, wid = tid >> 5;
        const int wM = wid >> 2, wN = wid & 3, g = lane >> 2, q = (lane & 3) * 2;
#pragma unroll
        for (int mi = 0; mi < 3; mi++)
#pragma unroll
            for (int nb = 0; nb < 4; nb++) {
                int r = wM * 48 + mi * 16 + g, c = wN * 32 + nb * 8 + q;
                float b0 = sm->b2[c], b1v = sm->b2[c + 1];
                store_h2(&sm->Ah[r * SA + 128 + c], &sm->Al[r * SA + 128 + c],
                         C[mi][nb][0] + b0, C[mi][nb][1] + b1v);
                store_h2(&sm->Ah[(r + 8) * SA + 128 + c], &sm->Al[(r + 8) * SA + 128 + c],
                         C[mi][nb][2] + b0, C[mi][nb][3] + b1v);
            }
    }
    __syncthreads();
    for (int i = tid; i < TILE * 16; i += NTH) {
        int e = i >> 4, s = (i & 15) * 8;
        if (e < rem) {
            *(uint4*)&g_e1h[(size_t)(e0 + e) * 128 + s] = *(const uint4*)&sm->Ah[e * SA + 128 + s];
            *(uint4*)&g_e1l[(size_t)(e0 + e) * 128 + s] = *(const uint4*)&sm->Al[e * SA + 128 + s];
        }
    }
    // MLP2: input cols [0,256) = [x[row], e1]
    stage_w(sm, 0, g_w + W_N1W1, 256, 0);
    cp_commit();
    if (tid < 128) sm->b1[tid] = n1b1[tid];
    run_gemm(sm, 0, 256, g_w + W_N1W1, C, 0);
    __syncthreads();
    hidden_epilogue(sm, C);
    stage_w(sm, 0, g_w + W_N1W2, 128, 0);
    cp_commit();
    if (tid < 128) sm->b2[tid] = n1b2[tid];
    run_gemm(sm, 256, 128, g_w + W_N1W2, C, 0);
    scatter_epilogue(sm, C, g_x1, rem);
}

// ---- Phase B ----
__global__ void __launch_bounds__(NTH, 1)
phaseB(const int* __restrict__ row, const int* __restrict__ col,
       const float* __restrict__ n2b1, const float* __restrict__ n2b2,
       float* __restrict__ x2out)
{
    extern __shared__ char raw[];
    SM* sm = (SM*)raw;
    const int tid = threadIdx.x;
    const int e0 = blockIdx.x * TILE;
    const int rem = min(TILE, NE - e0);

    load_idx(sm, row, col, e0);
    __syncthreads();

    stage_w(sm, 0, g_w + W_N2W1, 256, 0);
    gather_idx(sm, 0, g_x1h, g_x1l, sm->rowI);
    cp_commit();                                  // G1
    gather_edge(sm, 128, g_e1h, g_e1l, e0);
    cp_commit();                                  // G2
    if (tid < 128) sm->b1[tid] = n2b1[tid];

    float C[3][4][4];
    run_gemm(sm, 0, 256, g_w + W_N2W1, C, 1);
    __syncthreads();
    hidden_epilogue(sm, C);
    stage_w(sm, 0, g_w + W_N2W2, 128, 0);
    cp_commit();
    if (tid < 128) sm->b2[tid] = n2b2[tid];
    run_gemm(sm, 256, 128, g_w + W_N2W2, C, 0);
    scatter_epilogue(sm, C, x2out, rem);
}

// ---- Phase C ----
__global__ void __launch_bounds__(NTH, 1)
phaseC(const int* __restrict__ row, const int* __restrict__ col,
       const float* __restrict__ e2b1, const float* __restrict__ e2b2,
       float* __restrict__ e2out)
{
    extern __shared__ char raw[];
    SM* sm = (SM*)raw;
    const int tid = threadIdx.x;
    const int e0 = blockIdx.x * TILE;
    const int rem = min(TILE, NE - e0);

    load_idx(sm, row, col, e0);
    __syncthreads();

    stage_w(sm, 0, g_w + W_E2W1, 384, 0);
    gather_idx(sm, 0, g_x2h, g_x2l, sm->rowI);
    cp_commit();                                  // G1
    gather_idx(sm, 128, g_x2h, g_x2l, sm->colI);
    gather_edge(sm, 256, g_e1h, g_e1l, e0);
    cp_commit();                                  // G2
    if (tid < 128) sm->b1[tid] = e2b1[tid];

    float C[3][4][4];
    run_gemm(sm, 0, 384, g_w + W_E2W1, C, 1);
    __syncthreads();
    hidden_epilogue(sm, C);
    stage_w(sm, 0, g_w + W_E2W2, 128, 0);
    cp_commit();
    if (tid < 128) sm->b2[tid] = e2b2[tid];
    run_gemm(sm, 256, 128, g_w + W_E2W2, C, 0);
    __syncthreads();   // all reads done before reusing Ah as fp32 staging

    float* sE = (float*)sm->Ah;   // 96*128*4 = 48 KB
    {
        const int lane = tid & 31, wid = tid >> 5;
        const int wM = wid >> 2, wN = wid & 3, g = lane >> 2, q = (lane & 3) * 2;
#pragma unroll
        for (int mi = 0; mi < 3; mi++)
#pragma unroll
            for (int nb = 0; nb < 4; nb++) {
                int r = wM * 48 + mi * 16 + g, c = wN * 32 + nb * 8 + q;
                float b0 = sm->b2[c], b1v = sm->b2[c + 1];
                sE[r * 128 + c]           = C[mi][nb][0] + b0;
                sE[r * 128 + c + 1]       = C[mi][nb][1] + b1v;
                sE[(r + 8) * 128 + c]     = C[mi][nb][2] + b0;
                sE[(r + 8) * 128 + c + 1] = C[mi][nb][3] + b1v;
            }
    }
    __syncthreads();
    for (int i = tid; i < TILE * 32; i += NTH) {
        int e = i >> 5, s = (i & 31) * 4;
        if (e < rem)
            *(float4*)&e2out[(size_t)(e0 + e) * 128 + s] = *(const float4*)&sE[e * 128 + s];
    }
}

extern "C" void kernel_launch(void* const* d_in, const int* in_sizes, int n_in,
                              void* d_out, int out_size)
{
    const float* x    = (const float*)d_in[0];
    const float* ea   = (const float*)d_in[1];
    const int*   ei   = (const int*)d_in[2];
    const float* e1w1 = (const float*)d_in[3];
    const float* e1b1 = (const float*)d_in[4];
    const float* e1w2 = (const float*)d_in[5];
    const float* e1b2 = (const float*)d_in[6];
    const float* n1w1 = (const float*)d_in[7];
    const float* n1b1 = (const float*)d_in[8];
    const float* n1w2 = (const float*)d_in[9];
    const float* n1b2 = (const float*)d_in[10];
    const float* n2w1 = (const float*)d_in[11];
    const float* n2b1 = (const float*)d_in[12];
    const float* n2w2 = (const float*)d_in[13];
    const float* n2b2 = (const float*)d_in[14];
    const float* e2w1 = (const float*)d_in[15];
    const float* e2b1 = (const float*)d_in[16];
    const float* e2w2 = (const float*)d_in[17];
    const float* e2b2 = (const float*)d_in[18];

    const int* row = ei;
    const int* col = ei + NE;

    float* out = (float*)d_out;
    float* x2  = out;
    float* e2o = out + (size_t)NN * 128;

    __half *w, *xh, *xl, *e1h, *e1l, *x1h, *x1l, *x2h, *x2l;
    float* x1p;
    cudaGetSymbolAddress((void**)&w, g_w);
    cudaGetSymbolAddress((void**)&xh, g_xh);
    cudaGetSymbolAddress((void**)&xl, g_xl);
    cudaGetSymbolAddress((void**)&e1h, g_e1h);
    cudaGetSymbolAddress((void**)&e1l, g_e1l);
    cudaGetSymbolAddress((void**)&x1h, g_x1h);
    cudaGetSymbolAddress((void**)&x1l, g_x1l);
    cudaGetSymbolAddress((void**)&x2h, g_x2h);
    cudaGetSymbolAddress((void**)&x2l, g_x2l);
    cudaGetSymbolAddress((void**)&x1p, g_x1);

    wprep_all<<<(229376 + 255) / 256, 256>>>(e1w1, e1w2, n1w1, n1w2,
                                             n2w1, n2w2, e2w1, e2w2, w);
    zero_kernel<<<1024, NTH>>>(x2);
    prep_split<<<512, 256>>>(x,  xh, xl, (size_t)NN * 32);
    prep_split<<<2048, 256>>>(ea, e1h, e1l, (size_t)NE * 32);

    int smemBytes = (int)sizeof(SM);
    cudaFuncSetAttribute(phaseA, cudaFuncAttributeMaxDynamicSharedMemorySize, smemBytes);
    cudaFuncSetAttribute(phaseB, cudaFuncAttributeMaxDynamicSharedMemorySize, smemBytes);
    cudaFuncSetAttribute(phaseC, cudaFuncAttributeMaxDynamicSharedMemorySize, smemBytes);

    phaseA<<<NBLK, NTH, smemBytes>>>(row, col, e1b1, e1b2, n1b1, n1b2);
    prep_split<<<512, 256>>>(x1p, x1h, x1l, (size_t)NN * 32);
    phaseB<<<NBLK, NTH, smemBytes>>>(row, col, n2b1, n2b2, x2);
    prep_split<<<512, 256>>>(x2, x2h, x2l, (size_t)NN * 32);
    phaseC<<<NBLK, NTH, smemBytes>>>(row, col, e2b1, e2b2, e2o);
}